// round 4
// baseline (speedup 1.0000x reference)
#include <cuda_runtime.h>
#include <cuda_bf16.h>
#include <cstdint>

#define NN 100000
#define EE 1600000
#define D  128
#define KTOT 384

typedef unsigned long long ull;

// ---------------- scratch (static device globals; no allocation) -------------
__device__ float g_f1[(size_t)NN * D];
__device__ float g_f2[(size_t)NN * D];
__device__ int   g_deg[NN];
__device__ int   g_cursor[NN];
__device__ int   g_rowptr[NN + 1];
__device__ int2  g_dstval[EE];          // packed (dst, val-bits)
// Pre-swizzled bf16 hi/lo images of W: 6 K-chunks of [128 n][64 k] bf16 (16 KB each)
__device__ __align__(16) unsigned char g_Wh[6 * 16384];
__device__ __align__(16) unsigned char g_Wl[6 * 16384];

// ---------------- PTX helpers -------------------------------------------------
__device__ __forceinline__ uint32_t smem_u32(const void* p) {
    uint32_t a;
    asm("{ .reg .u64 t; cvta.to.shared.u64 t, %1; cvt.u32.u64 %0, t; }" : "=r"(a) : "l"(p));
    return a;
}

#define LDSM4(R, A)                                                         \
    asm volatile("ldmatrix.sync.aligned.m8n8.x4.shared.b16 "                \
                 "{%0,%1,%2,%3}, [%4];"                                     \
                 : "=r"((R)[0]), "=r"((R)[1]), "=r"((R)[2]), "=r"((R)[3])   \
                 : "r"(A))

#define MMA16816(DD, AA, B0, B1)                                            \
    asm volatile("mma.sync.aligned.m16n8k16.row.col.f32.bf16.bf16.f32 "     \
                 "{%0,%1,%2,%3},{%4,%5,%6,%7},{%8,%9},{%0,%1,%2,%3};"       \
                 : "+f"((DD)[0]), "+f"((DD)[1]), "+f"((DD)[2]), "+f"((DD)[3]) \
                 : "r"((AA)[0]), "r"((AA)[1]), "r"((AA)[2]), "r"((AA)[3]),  \
                   "r"(B0), "r"(B1))

__device__ __forceinline__ uint32_t swz(uint32_t bo) {
    return bo ^ ((bo >> 3) & 0x70);
}

// ---------------- CSR build ---------------------------------------------------
__global__ void zero_deg_kernel() {
    int i = blockIdx.x * blockDim.x + threadIdx.x;
    if (i < NN) g_deg[i] = 0;
}

__global__ void hist_kernel(const int* __restrict__ src) {
    int t = blockIdx.x * blockDim.x + threadIdx.x;   // 4 edges per thread
    int e = t * 4;
    if (e + 3 < EE) {
        int4 s = __ldg((const int4*)(src + e));
        atomicAdd(&g_deg[s.x], 1);
        atomicAdd(&g_deg[s.y], 1);
        atomicAdd(&g_deg[s.z], 1);
        atomicAdd(&g_deg[s.w], 1);
    } else {
        for (int q = e; q < EE; q++) atomicAdd(&g_deg[__ldg(src + q)], 1);
    }
}

__global__ void scan_kernel() {
    __shared__ int warpsums[32];
    __shared__ int s_carry;
    int tid = threadIdx.x, lane = tid & 31, wid = tid >> 5;
    if (tid == 0) s_carry = 0;
    __syncthreads();

    for (int base = 0; base < NN; base += 1024) {
        int i = base + tid;
        int v = (i < NN) ? g_deg[i] : 0;
        int val = v;
        #pragma unroll
        for (int off = 1; off < 32; off <<= 1) {
            int t = __shfl_up_sync(0xffffffffu, val, off);
            if (lane >= off) val += t;
        }
        if (lane == 31) warpsums[wid] = val;
        __syncthreads();
        if (wid == 0) {
            int w = warpsums[lane];
            #pragma unroll
            for (int off = 1; off < 32; off <<= 1) {
                int t = __shfl_up_sync(0xffffffffu, w, off);
                if (lane >= off) w += t;
            }
            warpsums[lane] = w;
        }
        __syncthreads();
        int carry = s_carry;
        int incl  = val + (wid > 0 ? warpsums[wid - 1] : 0);
        int excl  = incl - v + carry;
        if (i < NN) { g_rowptr[i] = excl; g_cursor[i] = excl; }
        int total = warpsums[31];
        __syncthreads();
        if (tid == 0) s_carry = carry + total;
        __syncthreads();
    }
    if (threadIdx.x == 0) g_rowptr[NN] = s_carry;
}

__global__ void scatter_kernel(const int* __restrict__ src,
                               const int* __restrict__ dst,
                               const float* __restrict__ val) {
    int e = blockIdx.x * blockDim.x + threadIdx.x;
    if (e < EE) {
        int d = __ldg(dst + e);
        float v = __ldg(val + e);
        int pos = atomicAdd(&g_cursor[__ldg(src + e)], 1);
        g_dstval[pos] = make_int2(d, __float_as_int(v));
    }
}

// ---------------- SpMM: one warp per row -------------------------------------
__global__ __launch_bounds__(256)
void spmm_kernel(const float4* __restrict__ fin, float4* __restrict__ fout) {
    int warp = (blockIdx.x * blockDim.x + threadIdx.x) >> 5;
    int lane = threadIdx.x & 31;
    if (warp >= NN) return;
    int beg = __ldg(&g_rowptr[warp]);
    int end = __ldg(&g_rowptr[warp + 1]);

    float4 acc = make_float4(0.f, 0.f, 0.f, 0.f);
    int j = beg;
    for (; j + 4 <= end; j += 4) {
        int2 m0 = __ldg(&g_dstval[j]);
        int2 m1 = __ldg(&g_dstval[j + 1]);
        int2 m2 = __ldg(&g_dstval[j + 2]);
        int2 m3 = __ldg(&g_dstval[j + 3]);
        float v0 = __int_as_float(m0.y), v1 = __int_as_float(m1.y);
        float v2 = __int_as_float(m2.y), v3 = __int_as_float(m3.y);
        float4 a0 = fin[(size_t)m0.x * 32 + lane];
        float4 a1 = fin[(size_t)m1.x * 32 + lane];
        float4 a2 = fin[(size_t)m2.x * 32 + lane];
        float4 a3 = fin[(size_t)m3.x * 32 + lane];
        acc.x = fmaf(v0, a0.x, fmaf(v1, a1.x, fmaf(v2, a2.x, fmaf(v3, a3.x, acc.x))));
        acc.y = fmaf(v0, a0.y, fmaf(v1, a1.y, fmaf(v2, a2.y, fmaf(v3, a3.y, acc.y))));
        acc.z = fmaf(v0, a0.z, fmaf(v1, a1.z, fmaf(v2, a2.z, fmaf(v3, a3.z, acc.z))));
        acc.w = fmaf(v0, a0.w, fmaf(v1, a1.w, fmaf(v2, a2.w, fmaf(v3, a3.w, acc.w))));
    }
    for (; j < end; j++) {
        int2 m = __ldg(&g_dstval[j]);
        float v = __int_as_float(m.y);
        float4 a = fin[(size_t)m.x * 32 + lane];
        acc.x = fmaf(v, a.x, acc.x);
        acc.y = fmaf(v, a.y, acc.y);
        acc.z = fmaf(v, a.z, acc.z);
        acc.w = fmaf(v, a.w, acc.w);
    }
    fout[(size_t)warp * 32 + lane] = acc;
}

// ---------------- W -> bf16 hi/lo, pre-swizzled SW128 chunks ------------------
__global__ void wconv_kernel(const float* __restrict__ W) {
    int i = blockIdx.x * blockDim.x + threadIdx.x;   // over 128 * 384
    if (i >= 128 * KTOT) return;
    int n = i / KTOT, k = i % KTOT;
    float v = W[i];
    __nv_bfloat16 h = __float2bfloat16(v);
    float rh = __bfloat162float(h);
    __nv_bfloat16 l = __float2bfloat16(v - rh);
    int c = k >> 6, kk = k & 63;
    uint32_t sw = swz((uint32_t)n * 128 + kk * 2);
    *(__nv_bfloat16*)(g_Wh + c * 16384 + sw) = h;
    *(__nv_bfloat16*)(g_Wl + c * 16384 + sw) = l;
}

// ---------------- partial-K mma.sync GEMM: out (+)= src @ Wc^T [+ b] ----------
// CTA: 128 rows x 128 cols, K=128 (two 64-chunks wc0, wc0+1), bf16 split-2.
// 8 warps as 4(m) x 2(n); warp tile 32x64. addbias!=0 -> write out with bias,
// else out += partial product (same thread layout across launches -> no race).
#define SMEM_GEMM_BYTES (1024 + 4 * 16384)

__global__ __launch_bounds__(256, 2)
void gemm_mma_kernel(const float* __restrict__ srcp,
                     const float* __restrict__ bias,
                     float* __restrict__ out,
                     int wc0, int addbias) {
    extern __shared__ unsigned char dsm[];
    const int tid  = threadIdx.x;
    const int lane = tid & 31;
    const int wid  = tid >> 5;
    const int warp_m = wid & 3;
    const int warp_n = wid >> 2;
    const int rbase  = blockIdx.x * 128;

    uint32_t sb0  = smem_u32(dsm);
    uint32_t base = (sb0 + 1023) & ~1023u;
    unsigned char* gp = dsm + (base - sb0);
    const uint32_t Ah = base, Al = base + 16384, Bh = base + 32768, Bl = base + 49152;

    auto load_chunk = [&](int c) {        // c in {0,1}
        const float4* s4 = (const float4*)srcp;
        int koff = c * 16;
        unsigned char* pAh = gp;
        unsigned char* pAl = gp + 16384;
        #pragma unroll
        for (int it = 0; it < 8; it++) {
            int idx = tid + it * 256;
            int row = idx >> 4, c4 = idx & 15;
            int grow = rbase + row;
            float4 v = make_float4(0.f, 0.f, 0.f, 0.f);
            if (grow < NN) v = s4[(size_t)grow * 32 + koff + c4];
            __nv_bfloat16 h0 = __float2bfloat16(v.x), h1 = __float2bfloat16(v.y);
            __nv_bfloat16 h2 = __float2bfloat16(v.z), h3 = __float2bfloat16(v.w);
            __nv_bfloat16 l0 = __float2bfloat16(v.x - __bfloat162float(h0));
            __nv_bfloat16 l1 = __float2bfloat16(v.y - __bfloat162float(h1));
            __nv_bfloat16 l2 = __float2bfloat16(v.z - __bfloat162float(h2));
            __nv_bfloat16 l3 = __float2bfloat16(v.w - __bfloat162float(h3));
            uint32_t hw0 = (uint32_t)__bfloat16_as_ushort(h0) |
                           ((uint32_t)__bfloat16_as_ushort(h1) << 16);
            uint32_t hw1 = (uint32_t)__bfloat16_as_ushort(h2) |
                           ((uint32_t)__bfloat16_as_ushort(h3) << 16);
            uint32_t lw0 = (uint32_t)__bfloat16_as_ushort(l0) |
                           ((uint32_t)__bfloat16_as_ushort(l1) << 16);
            uint32_t lw1 = (uint32_t)__bfloat16_as_ushort(l2) |
                           ((uint32_t)__bfloat16_as_ushort(l3) << 16);
            uint32_t sw = swz((uint32_t)row * 128 + c4 * 8);
            *(uint2*)(pAh + sw) = make_uint2(hw0, hw1);
            *(uint2*)(pAl + sw) = make_uint2(lw0, lw1);
        }
        const uint4* wh = (const uint4*)(g_Wh + (wc0 + c) * 16384);
        const uint4* wl = (const uint4*)(g_Wl + (wc0 + c) * 16384);
        uint4* pBh = (uint4*)(gp + 32768);
        uint4* pBl = (uint4*)(gp + 49152);
        #pragma unroll
        for (int it = 0; it < 4; it++) {
            int i = tid + it * 256;
            pBh[i] = wh[i];
            pBl[i] = wl[i];
        }
    };

    float acc[2][8][4];
    #pragma unroll
    for (int mf = 0; mf < 2; mf++)
        #pragma unroll
        for (int nf = 0; nf < 8; nf++)
            #pragma unroll
            for (int q = 0; q < 4; q++) acc[mf][nf][q] = 0.f;

    const int g = lane >> 3, r = lane & 7;
    const int a_row_off = r + (g & 1) * 8;
    const int a_k_off   = (g >> 1) * 8;
    const int b_n_off   = r + (g >> 1) * 8;
    const int b_k_off   = (g & 1) * 8;

    load_chunk(0);
    __syncthreads();

    #pragma unroll
    for (int c = 0; c < 2; c++) {
        #pragma unroll
        for (int ks = 0; ks < 4; ks++) {
            const int k0 = ks * 16;
            uint32_t ah[2][4], al[2][4];
            #pragma unroll
            for (int mf = 0; mf < 2; mf++) {
                uint32_t sw = swz((uint32_t)(warp_m * 32 + mf * 16 + a_row_off) * 128
                                  + (k0 + a_k_off) * 2);
                LDSM4(ah[mf], Ah + sw);
                LDSM4(al[mf], Al + sw);
            }
            #pragma unroll
            for (int bq = 0; bq < 4; bq++) {
                uint32_t sw = swz((uint32_t)(warp_n * 64 + bq * 16 + b_n_off) * 128
                                  + (k0 + b_k_off) * 2);
                uint32_t bh[4], bl[4];
                LDSM4(bh, Bh + sw);
                LDSM4(bl, Bl + sw);
                #pragma unroll
                for (int mf = 0; mf < 2; mf++) {
                    MMA16816(acc[mf][bq * 2 + 0], ah[mf], bh[0], bh[1]);
                    MMA16816(acc[mf][bq * 2 + 0], ah[mf], bl[0], bl[1]);
                    MMA16816(acc[mf][bq * 2 + 0], al[mf], bh[0], bh[1]);
                    MMA16816(acc[mf][bq * 2 + 1], ah[mf], bh[2], bh[3]);
                    MMA16816(acc[mf][bq * 2 + 1], ah[mf], bl[2], bl[3]);
                    MMA16816(acc[mf][bq * 2 + 1], al[mf], bh[2], bh[3]);
                }
            }
        }
        if (c == 0) {
            __syncthreads();
            load_chunk(1);
            __syncthreads();
        }
    }

    // ---- epilogue: bias (first launch) or accumulate into out ----
    const int qrow = lane >> 2, qcol = (lane & 3) * 2;
    #pragma unroll
    for (int nf = 0; nf < 8; nf++) {
        int col = warp_n * 64 + nf * 8 + qcol;
        float b0 = 0.f, b1 = 0.f;
        if (addbias) { b0 = __ldg(&bias[col]); b1 = __ldg(&bias[col + 1]); }
        #pragma unroll
        for (int mf = 0; mf < 2; mf++) {
            int row0 = rbase + warp_m * 32 + mf * 16 + qrow;
            if (row0 < NN) {
                float2* p = (float2*)(out + (size_t)row0 * 128 + col);
                float2 cur = addbias ? make_float2(b0, b1) : *p;
                *p = make_float2(cur.x + acc[mf][nf][0], cur.y + acc[mf][nf][1]);
            }
            int row1 = row0 + 8;
            if (row1 < NN) {
                float2* p = (float2*)(out + (size_t)row1 * 128 + col);
                float2 cur = addbias ? make_float2(b0, b1) : *p;
                *p = make_float2(cur.x + acc[mf][nf][2], cur.y + acc[mf][nf][3]);
            }
        }
    }
}

// ---------------- launch ------------------------------------------------------
extern "C" void kernel_launch(void* const* d_in, const int* in_sizes, int n_in,
                              void* d_out, int out_size) {
    const float* x        = (const float*)d_in[0];
    const int*   edge_src = (const int*)  d_in[1];
    const int*   edge_dst = (const int*)  d_in[2];
    const float* edge_val = (const float*)d_in[3];
    const float* W        = (const float*)d_in[4];
    const float* b        = (const float*)d_in[5];
    float* out = (float*)d_out;

    static bool init_done = false;
    static cudaStream_t s2;
    static cudaEvent_t ev_fork, ev_sp1, ev_g1;
    if (!init_done) {
        cudaFuncSetAttribute(gemm_mma_kernel,
                             cudaFuncAttributeMaxDynamicSharedMemorySize,
                             SMEM_GEMM_BYTES);
        cudaStreamCreateWithFlags(&s2, cudaStreamNonBlocking);
        cudaEventCreateWithFlags(&ev_fork, cudaEventDisableTiming);
        cudaEventCreateWithFlags(&ev_sp1,  cudaEventDisableTiming);
        cudaEventCreateWithFlags(&ev_g1,   cudaEventDisableTiming);
        init_done = true;
    }

    float *f1p, *f2p;
    cudaGetSymbolAddress((void**)&f1p, g_f1);
    cudaGetSymbolAddress((void**)&f2p, g_f2);

    const int GB = (NN + 127) / 128;     // 782 GEMM CTAs

    // Fork: side stream does W prep + x-part GEMM while main builds CSR.
    cudaEventRecord(ev_fork, 0);
    cudaStreamWaitEvent(s2, ev_fork, 0);
    wconv_kernel<<<(128 * KTOT + 255) / 256, 256, 0, s2>>>(W);
    gemm_mma_kernel<<<GB, 256, SMEM_GEMM_BYTES, s2>>>(x, b, out, 0, 1);

    // Main: CSR build + hop 1
    zero_deg_kernel<<<(NN + 255) / 256, 256>>>();
    hist_kernel<<<(EE / 4 + 255) / 256, 256>>>(edge_src);
    scan_kernel<<<1, 1024>>>();
    scatter_kernel<<<(EE + 255) / 256, 256>>>(edge_src, edge_dst, edge_val);
    int spmm_blocks = (NN + 7) / 8;
    spmm_kernel<<<spmm_blocks, 256>>>((const float4*)x, (float4*)f1p);
    cudaEventRecord(ev_sp1, 0);

    // Side: f1-part GEMM (after spmm1), overlaps hop 2
    cudaStreamWaitEvent(s2, ev_sp1, 0);
    gemm_mma_kernel<<<GB, 256, SMEM_GEMM_BYTES, s2>>>(f1p, b, out, 2, 0);
    cudaEventRecord(ev_g1, s2);

    // Main: hop 2, then join and do the f2-part GEMM tail
    spmm_kernel<<<spmm_blocks, 256>>>((const float4*)f1p, (float4*)f2p);
    cudaStreamWaitEvent(0, ev_g1, 0);
    gemm_mma_kernel<<<GB, 256, SMEM_GEMM_BYTES>>>(f2p, b, out, 4, 0);
}

// round 5
// speedup vs baseline: 1.1673x; 1.1673x over previous
#include <cuda_runtime.h>
#include <cuda_bf16.h>
#include <cstdint>

#define NN 100000
#define EE 1600000
#define D  128
#define KTOT 384

typedef unsigned long long ull;

// ---------------- scratch (static device globals; no allocation) -------------
__device__ float g_f1[(size_t)NN * D];
__device__ float g_f2[(size_t)NN * D];
__device__ int   g_deg[NN];
__device__ int   g_cursor[NN];
__device__ int   g_rowptr[NN + 1];
__device__ int2  g_dstval[EE];          // packed (dst, val-bits)
// Pre-swizzled bf16 hi/lo images of W: 6 K-chunks of [128 n][64 k] bf16 (16 KB each)
__device__ __align__(16) unsigned char g_Wh[6 * 16384];
__device__ __align__(16) unsigned char g_Wl[6 * 16384];

// ---------------- PTX helpers -------------------------------------------------
__device__ __forceinline__ uint32_t smem_u32(const void* p) {
    uint32_t a;
    asm("{ .reg .u64 t; cvta.to.shared.u64 t, %1; cvt.u32.u64 %0, t; }" : "=r"(a) : "l"(p));
    return a;
}

#define LDSM4(R, A)                                                         \
    asm volatile("ldmatrix.sync.aligned.m8n8.x4.shared.b16 "                \
                 "{%0,%1,%2,%3}, [%4];"                                     \
                 : "=r"((R)[0]), "=r"((R)[1]), "=r"((R)[2]), "=r"((R)[3])   \
                 : "r"(A))

#define MMA16816(DD, AA, B0, B1)                                            \
    asm volatile("mma.sync.aligned.m16n8k16.row.col.f32.bf16.bf16.f32 "     \
                 "{%0,%1,%2,%3},{%4,%5,%6,%7},{%8,%9},{%0,%1,%2,%3};"       \
                 : "+f"((DD)[0]), "+f"((DD)[1]), "+f"((DD)[2]), "+f"((DD)[3]) \
                 : "r"((AA)[0]), "r"((AA)[1]), "r"((AA)[2]), "r"((AA)[3]),  \
                   "r"(B0), "r"(B1))

__device__ __forceinline__ uint32_t swz(uint32_t bo) {
    return bo ^ ((bo >> 3) & 0x70);
}

// ---------------- CSR build ---------------------------------------------------
__global__ void zero_deg_kernel() {
    int i = blockIdx.x * blockDim.x + threadIdx.x;
    if (i < NN) g_deg[i] = 0;
}

__global__ void hist_kernel(const int* __restrict__ src) {
    int t = blockIdx.x * blockDim.x + threadIdx.x;   // 4 edges per thread
    int e = t * 4;
    if (e + 3 < EE) {
        int4 s = __ldg((const int4*)(src + e));
        atomicAdd(&g_deg[s.x], 1);
        atomicAdd(&g_deg[s.y], 1);
        atomicAdd(&g_deg[s.z], 1);
        atomicAdd(&g_deg[s.w], 1);
    } else {
        for (int q = e; q < EE; q++) atomicAdd(&g_deg[__ldg(src + q)], 1);
    }
}

__global__ void scan_kernel() {
    __shared__ int warpsums[32];
    __shared__ int s_carry;
    int tid = threadIdx.x, lane = tid & 31, wid = tid >> 5;
    if (tid == 0) s_carry = 0;
    __syncthreads();

    for (int base = 0; base < NN; base += 1024) {
        int i = base + tid;
        int v = (i < NN) ? g_deg[i] : 0;
        int val = v;
        #pragma unroll
        for (int off = 1; off < 32; off <<= 1) {
            int t = __shfl_up_sync(0xffffffffu, val, off);
            if (lane >= off) val += t;
        }
        if (lane == 31) warpsums[wid] = val;
        __syncthreads();
        if (wid == 0) {
            int w = warpsums[lane];
            #pragma unroll
            for (int off = 1; off < 32; off <<= 1) {
                int t = __shfl_up_sync(0xffffffffu, w, off);
                if (lane >= off) w += t;
            }
            warpsums[lane] = w;
        }
        __syncthreads();
        int carry = s_carry;
        int incl  = val + (wid > 0 ? warpsums[wid - 1] : 0);
        int excl  = incl - v + carry;
        if (i < NN) { g_rowptr[i] = excl; g_cursor[i] = excl; }
        int total = warpsums[31];
        __syncthreads();
        if (tid == 0) s_carry = carry + total;
        __syncthreads();
    }
    if (threadIdx.x == 0) g_rowptr[NN] = s_carry;
}

// Coarsened x4: four outstanding position-atomics per thread (hide ATOMG latency)
__global__ void scatter_kernel(const int* __restrict__ src,
                               const int* __restrict__ dst,
                               const float* __restrict__ val) {
    int t = blockIdx.x * blockDim.x + threadIdx.x;
    int e = t * 4;
    if (e + 3 < EE) {
        int4   s = __ldg((const int4*)(src + e));
        int4   d = __ldg((const int4*)(dst + e));
        float4 v = __ldg((const float4*)(val + e));
        int p0 = atomicAdd(&g_cursor[s.x], 1);
        int p1 = atomicAdd(&g_cursor[s.y], 1);
        int p2 = atomicAdd(&g_cursor[s.z], 1);
        int p3 = atomicAdd(&g_cursor[s.w], 1);
        g_dstval[p0] = make_int2(d.x, __float_as_int(v.x));
        g_dstval[p1] = make_int2(d.y, __float_as_int(v.y));
        g_dstval[p2] = make_int2(d.z, __float_as_int(v.z));
        g_dstval[p3] = make_int2(d.w, __float_as_int(v.w));
    } else {
        for (int q = e; q < EE; q++) {
            int dd = __ldg(dst + q);
            float vv = __ldg(val + q);
            int pos = atomicAdd(&g_cursor[__ldg(src + q)], 1);
            g_dstval[pos] = make_int2(dd, __float_as_int(vv));
        }
    }
}

// ---------------- SpMM: one warp per row -------------------------------------
__global__ __launch_bounds__(256)
void spmm_kernel(const float4* __restrict__ fin, float4* __restrict__ fout) {
    int warp = (blockIdx.x * blockDim.x + threadIdx.x) >> 5;
    int lane = threadIdx.x & 31;
    if (warp >= NN) return;
    int beg = __ldg(&g_rowptr[warp]);
    int end = __ldg(&g_rowptr[warp + 1]);

    float4 acc = make_float4(0.f, 0.f, 0.f, 0.f);
    int j = beg;
    for (; j + 4 <= end; j += 4) {
        int2 m0 = __ldg(&g_dstval[j]);
        int2 m1 = __ldg(&g_dstval[j + 1]);
        int2 m2 = __ldg(&g_dstval[j + 2]);
        int2 m3 = __ldg(&g_dstval[j + 3]);
        float v0 = __int_as_float(m0.y), v1 = __int_as_float(m1.y);
        float v2 = __int_as_float(m2.y), v3 = __int_as_float(m3.y);
        float4 a0 = fin[(size_t)m0.x * 32 + lane];
        float4 a1 = fin[(size_t)m1.x * 32 + lane];
        float4 a2 = fin[(size_t)m2.x * 32 + lane];
        float4 a3 = fin[(size_t)m3.x * 32 + lane];
        acc.x = fmaf(v0, a0.x, fmaf(v1, a1.x, fmaf(v2, a2.x, fmaf(v3, a3.x, acc.x))));
        acc.y = fmaf(v0, a0.y, fmaf(v1, a1.y, fmaf(v2, a2.y, fmaf(v3, a3.y, acc.y))));
        acc.z = fmaf(v0, a0.z, fmaf(v1, a1.z, fmaf(v2, a2.z, fmaf(v3, a3.z, acc.z))));
        acc.w = fmaf(v0, a0.w, fmaf(v1, a1.w, fmaf(v2, a2.w, fmaf(v3, a3.w, acc.w))));
    }
    for (; j < end; j++) {
        int2 m = __ldg(&g_dstval[j]);
        float v = __int_as_float(m.y);
        float4 a = fin[(size_t)m.x * 32 + lane];
        acc.x = fmaf(v, a.x, acc.x);
        acc.y = fmaf(v, a.y, acc.y);
        acc.z = fmaf(v, a.z, acc.z);
        acc.w = fmaf(v, a.w, acc.w);
    }
    fout[(size_t)warp * 32 + lane] = acc;
}

// ---------------- W -> bf16 hi/lo, pre-swizzled SW128 chunks ------------------
__global__ void wconv_kernel(const float* __restrict__ W) {
    int i = blockIdx.x * blockDim.x + threadIdx.x;   // over 128 * 384
    if (i >= 128 * KTOT) return;
    int n = i / KTOT, k = i % KTOT;
    float v = W[i];
    __nv_bfloat16 h = __float2bfloat16(v);
    float rh = __bfloat162float(h);
    __nv_bfloat16 l = __float2bfloat16(v - rh);
    int c = k >> 6, kk = k & 63;
    uint32_t sw = swz((uint32_t)n * 128 + kk * 2);
    *(__nv_bfloat16*)(g_Wh + c * 16384 + sw) = h;
    *(__nv_bfloat16*)(g_Wl + c * 16384 + sw) = l;
}

// ---------------- mma.sync GEMM: out = [x|f1|f2] @ W^T + b --------------------
// CTA: 128 rows x 128 cols, K=384 in six 64-chunks, bf16 split-2 (3 products).
// 8 warps as 4(m) x 2(n); warp tile 32x64. Fragments via ldmatrix from SW128 SMEM.
#define SMEM_GEMM_BYTES (1024 + 4 * 16384)

__global__ __launch_bounds__(256, 2)
void gemm_mma_kernel(const float* __restrict__ x,
                     const float* __restrict__ bias,
                     float* __restrict__ out) {
    extern __shared__ unsigned char dsm[];
    const int tid  = threadIdx.x;
    const int lane = tid & 31;
    const int wid  = tid >> 5;
    const int warp_m = wid & 3;
    const int warp_n = wid >> 2;
    const int rbase  = blockIdx.x * 128;

    uint32_t sb0  = smem_u32(dsm);
    uint32_t base = (sb0 + 1023) & ~1023u;
    unsigned char* gp = dsm + (base - sb0);
    const uint32_t Ah = base, Al = base + 16384, Bh = base + 32768, Bl = base + 49152;

    auto load_chunk = [&](int c) {
        const float* srcp = (c < 2) ? x : (c < 4) ? g_f1 : g_f2;
        const float4* s4 = (const float4*)srcp;
        int koff = (c & 1) * 16;
        unsigned char* pAh = gp;
        unsigned char* pAl = gp + 16384;
        #pragma unroll
        for (int it = 0; it < 8; it++) {
            int idx = tid + it * 256;
            int row = idx >> 4, c4 = idx & 15;
            int grow = rbase + row;
            float4 v = make_float4(0.f, 0.f, 0.f, 0.f);
            if (grow < NN) v = s4[(size_t)grow * 32 + koff + c4];
            __nv_bfloat16 h0 = __float2bfloat16(v.x), h1 = __float2bfloat16(v.y);
            __nv_bfloat16 h2 = __float2bfloat16(v.z), h3 = __float2bfloat16(v.w);
            __nv_bfloat16 l0 = __float2bfloat16(v.x - __bfloat162float(h0));
            __nv_bfloat16 l1 = __float2bfloat16(v.y - __bfloat162float(h1));
            __nv_bfloat16 l2 = __float2bfloat16(v.z - __bfloat162float(h2));
            __nv_bfloat16 l3 = __float2bfloat16(v.w - __bfloat162float(h3));
            uint32_t hw0 = (uint32_t)__bfloat16_as_ushort(h0) |
                           ((uint32_t)__bfloat16_as_ushort(h1) << 16);
            uint32_t hw1 = (uint32_t)__bfloat16_as_ushort(h2) |
                           ((uint32_t)__bfloat16_as_ushort(h3) << 16);
            uint32_t lw0 = (uint32_t)__bfloat16_as_ushort(l0) |
                           ((uint32_t)__bfloat16_as_ushort(l1) << 16);
            uint32_t lw1 = (uint32_t)__bfloat16_as_ushort(l2) |
                           ((uint32_t)__bfloat16_as_ushort(l3) << 16);
            uint32_t sw = swz((uint32_t)row * 128 + c4 * 8);
            *(uint2*)(pAh + sw) = make_uint2(hw0, hw1);
            *(uint2*)(pAl + sw) = make_uint2(lw0, lw1);
        }
        const uint4* wh = (const uint4*)(g_Wh + c * 16384);
        const uint4* wl = (const uint4*)(g_Wl + c * 16384);
        uint4* pBh = (uint4*)(gp + 32768);
        uint4* pBl = (uint4*)(gp + 49152);
        #pragma unroll
        for (int it = 0; it < 4; it++) {
            int i = tid + it * 256;
            pBh[i] = wh[i];
            pBl[i] = wl[i];
        }
    };

    float acc[2][8][4];
    #pragma unroll
    for (int mf = 0; mf < 2; mf++)
        #pragma unroll
        for (int nf = 0; nf < 8; nf++)
            #pragma unroll
            for (int q = 0; q < 4; q++) acc[mf][nf][q] = 0.f;

    const int g = lane >> 3, r = lane & 7;
    const int a_row_off = r + (g & 1) * 8;
    const int a_k_off   = (g >> 1) * 8;
    const int b_n_off   = r + (g >> 1) * 8;
    const int b_k_off   = (g & 1) * 8;

    load_chunk(0);
    __syncthreads();

    for (int c = 0; c < 6; c++) {
        #pragma unroll
        for (int ks = 0; ks < 4; ks++) {
            const int k0 = ks * 16;
            uint32_t ah[2][4], al[2][4];
            #pragma unroll
            for (int mf = 0; mf < 2; mf++) {
                uint32_t sw = swz((uint32_t)(warp_m * 32 + mf * 16 + a_row_off) * 128
                                  + (k0 + a_k_off) * 2);
                LDSM4(ah[mf], Ah + sw);
                LDSM4(al[mf], Al + sw);
            }
            #pragma unroll
            for (int bq = 0; bq < 4; bq++) {
                uint32_t sw = swz((uint32_t)(warp_n * 64 + bq * 16 + b_n_off) * 128
                                  + (k0 + b_k_off) * 2);
                uint32_t bh[4], bl[4];
                LDSM4(bh, Bh + sw);
                LDSM4(bl, Bl + sw);
                #pragma unroll
                for (int mf = 0; mf < 2; mf++) {
                    MMA16816(acc[mf][bq * 2 + 0], ah[mf], bh[0], bh[1]);
                    MMA16816(acc[mf][bq * 2 + 0], ah[mf], bl[0], bl[1]);
                    MMA16816(acc[mf][bq * 2 + 0], al[mf], bh[0], bh[1]);
                    MMA16816(acc[mf][bq * 2 + 1], ah[mf], bh[2], bh[3]);
                    MMA16816(acc[mf][bq * 2 + 1], ah[mf], bl[2], bl[3]);
                    MMA16816(acc[mf][bq * 2 + 1], al[mf], bh[2], bh[3]);
                }
            }
        }
        if (c < 5) {
            __syncthreads();
            load_chunk(c + 1);
            __syncthreads();
        }
    }

    // ---- epilogue: bias + store ----
    const int qrow = lane >> 2, qcol = (lane & 3) * 2;
    #pragma unroll
    for (int nf = 0; nf < 8; nf++) {
        int col = warp_n * 64 + nf * 8 + qcol;
        float b0 = __ldg(&bias[col]);
        float b1 = __ldg(&bias[col + 1]);
        #pragma unroll
        for (int mf = 0; mf < 2; mf++) {
            int row0 = rbase + warp_m * 32 + mf * 16 + qrow;
            if (row0 < NN)
                *(float2*)(out + (size_t)row0 * 128 + col) =
                    make_float2(acc[mf][nf][0] + b0, acc[mf][nf][1] + b1);
            int row1 = row0 + 8;
            if (row1 < NN)
                *(float2*)(out + (size_t)row1 * 128 + col) =
                    make_float2(acc[mf][nf][2] + b0, acc[mf][nf][3] + b1);
        }
    }
}

// ---------------- launch ------------------------------------------------------
extern "C" void kernel_launch(void* const* d_in, const int* in_sizes, int n_in,
                              void* d_out, int out_size) {
    const float* x        = (const float*)d_in[0];
    const int*   edge_src = (const int*)  d_in[1];
    const int*   edge_dst = (const int*)  d_in[2];
    const float* edge_val = (const float*)d_in[3];
    const float* W        = (const float*)d_in[4];
    const float* b        = (const float*)d_in[5];
    float* out = (float*)d_out;

    static bool attr_set = false;
    if (!attr_set) {
        cudaFuncSetAttribute(gemm_mma_kernel,
                             cudaFuncAttributeMaxDynamicSharedMemorySize,
                             SMEM_GEMM_BYTES);
        attr_set = true;
    }

    float *f1p, *f2p;
    cudaGetSymbolAddress((void**)&f1p, g_f1);
    cudaGetSymbolAddress((void**)&f2p, g_f2);

    // 1) W prep (independent, tiny) + CSR build
    wconv_kernel<<<(128 * KTOT + 255) / 256, 256>>>(W);
    zero_deg_kernel<<<(NN + 255) / 256, 256>>>();
    hist_kernel<<<(EE / 4 + 255) / 256, 256>>>(edge_src);
    scan_kernel<<<1, 1024>>>();
    scatter_kernel<<<(EE / 4 + 255) / 256, 256>>>(edge_src, edge_dst, edge_val);

    // 2) Two SpMM hops
    int spmm_blocks = (NN + 7) / 8;
    spmm_kernel<<<spmm_blocks, 256>>>((const float4*)x,  (float4*)f1p);
    spmm_kernel<<<spmm_blocks, 256>>>((const float4*)f1p, (float4*)f2p);

    // 3) Tensor-core dense layer on [x | f1 | f2]
    gemm_mma_kernel<<<(NN + 127) / 128, 256, SMEM_GEMM_BYTES>>>(x, b, out);
}

// round 6
// speedup vs baseline: 1.4179x; 1.2147x over previous
#include <cuda_runtime.h>
#include <cuda_bf16.h>
#include <cstdint>

#define NN 100000
#define EE 1600000
#define D  128
#define KTOT 384
#define NB  ((NN + 1023) / 1024)   // 98 scan blocks

typedef unsigned long long ull;

// ---------------- scratch (static device globals; no allocation) -------------
__device__ float g_f1[(size_t)NN * D];
__device__ float g_f2[(size_t)NN * D];
__device__ int   g_deg[NN];
__device__ int   g_cursor[NN];
__device__ int   g_rowptr[NN + 1];
__device__ int   g_blocksum[NB];
__device__ int   g_blockoff[NB];
__device__ int2  g_dstval[EE];          // packed (dst, val-bits)
// Pre-swizzled bf16 hi/lo images of W: 6 K-chunks of [128 n][64 k] bf16 (16 KB each)
__device__ __align__(16) unsigned char g_Wh[6 * 16384];
__device__ __align__(16) unsigned char g_Wl[6 * 16384];

// ---------------- PTX helpers -------------------------------------------------
__device__ __forceinline__ uint32_t smem_u32(const void* p) {
    uint32_t a;
    asm("{ .reg .u64 t; cvta.to.shared.u64 t, %1; cvt.u32.u64 %0, t; }" : "=r"(a) : "l"(p));
    return a;
}

#define LDSM4(R, A)                                                         \
    asm volatile("ldmatrix.sync.aligned.m8n8.x4.shared.b16 "                \
                 "{%0,%1,%2,%3}, [%4];"                                     \
                 : "=r"((R)[0]), "=r"((R)[1]), "=r"((R)[2]), "=r"((R)[3])   \
                 : "r"(A))

#define MMA16816(DD, AA, B0, B1)                                            \
    asm volatile("mma.sync.aligned.m16n8k16.row.col.f32.bf16.bf16.f32 "     \
                 "{%0,%1,%2,%3},{%4,%5,%6,%7},{%8,%9},{%0,%1,%2,%3};"       \
                 : "+f"((DD)[0]), "+f"((DD)[1]), "+f"((DD)[2]), "+f"((DD)[3]) \
                 : "r"((AA)[0]), "r"((AA)[1]), "r"((AA)[2]), "r"((AA)[3]),  \
                   "r"(B0), "r"(B1))

__device__ __forceinline__ uint32_t swz(uint32_t bo) {
    return bo ^ ((bo >> 3) & 0x70);
}

__device__ __forceinline__ int warp_incl_scan(int val, int lane) {
    #pragma unroll
    for (int off = 1; off < 32; off <<= 1) {
        int t = __shfl_up_sync(0xffffffffu, val, off);
        if (lane >= off) val += t;
    }
    return val;
}

// ---------------- CSR build ---------------------------------------------------
__global__ void zero_deg_kernel() {
    int i = blockIdx.x * blockDim.x + threadIdx.x;
    if (i < NN) g_deg[i] = 0;
}

__global__ void hist_kernel(const int* __restrict__ src) {
    int t = blockIdx.x * blockDim.x + threadIdx.x;   // 4 edges per thread
    int e = t * 4;
    if (e + 3 < EE) {
        int4 s = __ldg((const int4*)(src + e));
        atomicAdd(&g_deg[s.x], 1);
        atomicAdd(&g_deg[s.y], 1);
        atomicAdd(&g_deg[s.z], 1);
        atomicAdd(&g_deg[s.w], 1);
    } else {
        for (int q = e; q < EE; q++) atomicAdd(&g_deg[__ldg(src + q)], 1);
    }
}

// ---- two-level parallel scan: local per-block -> tops -> add offsets --------
__global__ __launch_bounds__(1024)
void scan_local_kernel() {
    __shared__ int warpsums[32];
    int tid = threadIdx.x, lane = tid & 31, wid = tid >> 5;
    int i = blockIdx.x * 1024 + tid;
    int v = (i < NN) ? g_deg[i] : 0;
    int val = warp_incl_scan(v, lane);
    if (lane == 31) warpsums[wid] = val;
    __syncthreads();
    if (wid == 0) warpsums[lane] = warp_incl_scan(warpsums[lane], lane);
    __syncthreads();
    int excl = val - v + (wid > 0 ? warpsums[wid - 1] : 0);
    if (i < NN) g_rowptr[i] = excl;              // local exclusive scan
    if (tid == 0) g_blocksum[blockIdx.x] = warpsums[31];
}

__global__ __launch_bounds__(128)
void scan_tops_kernel() {
    __shared__ int ws[4];
    int tid = threadIdx.x, lane = tid & 31, wid = tid >> 5;
    int v = (tid < NB) ? g_blocksum[tid] : 0;
    int val = warp_incl_scan(v, lane);
    if (lane == 31) ws[wid] = val;
    __syncthreads();
    if (tid == 0) {
        int a = ws[0];
        ws[0] = 0;
        #pragma unroll
        for (int q = 1; q < 4; q++) { int t = ws[q]; ws[q] = a; a += t; }
    }
    __syncthreads();
    if (tid < NB) g_blockoff[tid] = val - v + ws[wid];
}

__global__ void scan_add_kernel() {
    int i = blockIdx.x * blockDim.x + threadIdx.x;
    if (i < NN) {
        int r = g_rowptr[i] + g_blockoff[i >> 10];
        g_rowptr[i] = r;
        g_cursor[i] = r;
    }
    if (i == 0) g_rowptr[NN] = EE;
}

// Coarsened x4: four outstanding position-atomics per thread (hide ATOMG latency)
__global__ void scatter_kernel(const int* __restrict__ src,
                               const int* __restrict__ dst,
                               const float* __restrict__ val) {
    int t = blockIdx.x * blockDim.x + threadIdx.x;
    int e = t * 4;
    if (e + 3 < EE) {
        int4   s = __ldg((const int4*)(src + e));
        int4   d = __ldg((const int4*)(dst + e));
        float4 v = __ldg((const float4*)(val + e));
        int p0 = atomicAdd(&g_cursor[s.x], 1);
        int p1 = atomicAdd(&g_cursor[s.y], 1);
        int p2 = atomicAdd(&g_cursor[s.z], 1);
        int p3 = atomicAdd(&g_cursor[s.w], 1);
        g_dstval[p0] = make_int2(d.x, __float_as_int(v.x));
        g_dstval[p1] = make_int2(d.y, __float_as_int(v.y));
        g_dstval[p2] = make_int2(d.z, __float_as_int(v.z));
        g_dstval[p3] = make_int2(d.w, __float_as_int(v.w));
    } else {
        for (int q = e; q < EE; q++) {
            int dd = __ldg(dst + q);
            float vv = __ldg(val + q);
            int pos = atomicAdd(&g_cursor[__ldg(src + q)], 1);
            g_dstval[pos] = make_int2(dd, __float_as_int(vv));
        }
    }
}

// ---------------- SpMM: one warp per row -------------------------------------
__global__ __launch_bounds__(256)
void spmm_kernel(const float4* __restrict__ fin, float4* __restrict__ fout) {
    int warp = (blockIdx.x * blockDim.x + threadIdx.x) >> 5;
    int lane = threadIdx.x & 31;
    if (warp >= NN) return;
    int beg = __ldg(&g_rowptr[warp]);
    int end = __ldg(&g_rowptr[warp + 1]);

    float4 acc = make_float4(0.f, 0.f, 0.f, 0.f);
    int j = beg;
    for (; j + 4 <= end; j += 4) {
        int2 m0 = __ldg(&g_dstval[j]);
        int2 m1 = __ldg(&g_dstval[j + 1]);
        int2 m2 = __ldg(&g_dstval[j + 2]);
        int2 m3 = __ldg(&g_dstval[j + 3]);
        float v0 = __int_as_float(m0.y), v1 = __int_as_float(m1.y);
        float v2 = __int_as_float(m2.y), v3 = __int_as_float(m3.y);
        float4 a0 = fin[(size_t)m0.x * 32 + lane];
        float4 a1 = fin[(size_t)m1.x * 32 + lane];
        float4 a2 = fin[(size_t)m2.x * 32 + lane];
        float4 a3 = fin[(size_t)m3.x * 32 + lane];
        acc.x = fmaf(v0, a0.x, fmaf(v1, a1.x, fmaf(v2, a2.x, fmaf(v3, a3.x, acc.x))));
        acc.y = fmaf(v0, a0.y, fmaf(v1, a1.y, fmaf(v2, a2.y, fmaf(v3, a3.y, acc.y))));
        acc.z = fmaf(v0, a0.z, fmaf(v1, a1.z, fmaf(v2, a2.z, fmaf(v3, a3.z, acc.z))));
        acc.w = fmaf(v0, a0.w, fmaf(v1, a1.w, fmaf(v2, a2.w, fmaf(v3, a3.w, acc.w))));
    }
    for (; j < end; j++) {
        int2 m = __ldg(&g_dstval[j]);
        float v = __int_as_float(m.y);
        float4 a = fin[(size_t)m.x * 32 + lane];
        acc.x = fmaf(v, a.x, acc.x);
        acc.y = fmaf(v, a.y, acc.y);
        acc.z = fmaf(v, a.z, acc.z);
        acc.w = fmaf(v, a.w, acc.w);
    }
    fout[(size_t)warp * 32 + lane] = acc;
}

// ---------------- W -> bf16 hi/lo, pre-swizzled SW128 chunks ------------------
__global__ void wconv_kernel(const float* __restrict__ W) {
    int i = blockIdx.x * blockDim.x + threadIdx.x;   // over 128 * 384
    if (i >= 128 * KTOT) return;
    int n = i / KTOT, k = i % KTOT;
    float v = W[i];
    __nv_bfloat16 h = __float2bfloat16(v);
    float rh = __bfloat162float(h);
    __nv_bfloat16 l = __float2bfloat16(v - rh);
    int c = k >> 6, kk = k & 63;
    uint32_t sw = swz((uint32_t)n * 128 + kk * 2);
    *(__nv_bfloat16*)(g_Wh + c * 16384 + sw) = h;
    *(__nv_bfloat16*)(g_Wl + c * 16384 + sw) = l;
}

// ---------------- mma.sync GEMM: out = [x|f1|f2] @ W^T + b --------------------
// CTA: 128 rows x 128 cols, K=384 in six 64-chunks, bf16 split-2 (3 products).
// 8 warps as 4(m) x 2(n); warp tile 32x64. Fragments via ldmatrix from SW128 SMEM.
#define SMEM_GEMM_BYTES (1024 + 4 * 16384)

__global__ __launch_bounds__(256, 2)
void gemm_mma_kernel(const float* __restrict__ x,
                     const float* __restrict__ bias,
                     float* __restrict__ out) {
    extern __shared__ unsigned char dsm[];
    const int tid  = threadIdx.x;
    const int lane = tid & 31;
    const int wid  = tid >> 5;
    const int warp_m = wid & 3;
    const int warp_n = wid >> 2;
    const int rbase  = blockIdx.x * 128;

    uint32_t sb0  = smem_u32(dsm);
    uint32_t base = (sb0 + 1023) & ~1023u;
    unsigned char* gp = dsm + (base - sb0);
    const uint32_t Ah = base, Al = base + 16384, Bh = base + 32768, Bl = base + 49152;

    auto load_chunk = [&](int c) {
        const float* srcp = (c < 2) ? x : (c < 4) ? g_f1 : g_f2;
        const float4* s4 = (const float4*)srcp;
        int koff = (c & 1) * 16;
        unsigned char* pAh = gp;
        unsigned char* pAl = gp + 16384;
        #pragma unroll
        for (int it = 0; it < 8; it++) {
            int idx = tid + it * 256;
            int row = idx >> 4, c4 = idx & 15;
            int grow = rbase + row;
            float4 v = make_float4(0.f, 0.f, 0.f, 0.f);
            if (grow < NN) v = s4[(size_t)grow * 32 + koff + c4];
            __nv_bfloat16 h0 = __float2bfloat16(v.x), h1 = __float2bfloat16(v.y);
            __nv_bfloat16 h2 = __float2bfloat16(v.z), h3 = __float2bfloat16(v.w);
            __nv_bfloat16 l0 = __float2bfloat16(v.x - __bfloat162float(h0));
            __nv_bfloat16 l1 = __float2bfloat16(v.y - __bfloat162float(h1));
            __nv_bfloat16 l2 = __float2bfloat16(v.z - __bfloat162float(h2));
            __nv_bfloat16 l3 = __float2bfloat16(v.w - __bfloat162float(h3));
            uint32_t hw0 = (uint32_t)__bfloat16_as_ushort(h0) |
                           ((uint32_t)__bfloat16_as_ushort(h1) << 16);
            uint32_t hw1 = (uint32_t)__bfloat16_as_ushort(h2) |
                           ((uint32_t)__bfloat16_as_ushort(h3) << 16);
            uint32_t lw0 = (uint32_t)__bfloat16_as_ushort(l0) |
                           ((uint32_t)__bfloat16_as_ushort(l1) << 16);
            uint32_t lw1 = (uint32_t)__bfloat16_as_ushort(l2) |
                           ((uint32_t)__bfloat16_as_ushort(l3) << 16);
            uint32_t sw = swz((uint32_t)row * 128 + c4 * 8);
            *(uint2*)(pAh + sw) = make_uint2(hw0, hw1);
            *(uint2*)(pAl + sw) = make_uint2(lw0, lw1);
        }
        const uint4* wh = (const uint4*)(g_Wh + c * 16384);
        const uint4* wl = (const uint4*)(g_Wl + c * 16384);
        uint4* pBh = (uint4*)(gp + 32768);
        uint4* pBl = (uint4*)(gp + 49152);
        #pragma unroll
        for (int it = 0; it < 4; it++) {
            int i = tid + it * 256;
            pBh[i] = wh[i];
            pBl[i] = wl[i];
        }
    };

    float acc[2][8][4];
    #pragma unroll
    for (int mf = 0; mf < 2; mf++)
        #pragma unroll
        for (int nf = 0; nf < 8; nf++)
            #pragma unroll
            for (int q = 0; q < 4; q++) acc[mf][nf][q] = 0.f;

    const int g = lane >> 3, r = lane & 7;
    const int a_row_off = r + (g & 1) * 8;
    const int a_k_off   = (g >> 1) * 8;
    const int b_n_off   = r + (g >> 1) * 8;
    const int b_k_off   = (g & 1) * 8;

    load_chunk(0);
    __syncthreads();

    for (int c = 0; c < 6; c++) {
        #pragma unroll
        for (int ks = 0; ks < 4; ks++) {
            const int k0 = ks * 16;
            uint32_t ah[2][4], al[2][4];
            #pragma unroll
            for (int mf = 0; mf < 2; mf++) {
                uint32_t sw = swz((uint32_t)(warp_m * 32 + mf * 16 + a_row_off) * 128
                                  + (k0 + a_k_off) * 2);
                LDSM4(ah[mf], Ah + sw);
                LDSM4(al[mf], Al + sw);
            }
            #pragma unroll
            for (int bq = 0; bq < 4; bq++) {
                uint32_t sw = swz((uint32_t)(warp_n * 64 + bq * 16 + b_n_off) * 128
                                  + (k0 + b_k_off) * 2);
                uint32_t bh[4], bl[4];
                LDSM4(bh, Bh + sw);
                LDSM4(bl, Bl + sw);
                #pragma unroll
                for (int mf = 0; mf < 2; mf++) {
                    MMA16816(acc[mf][bq * 2 + 0], ah[mf], bh[0], bh[1]);
                    MMA16816(acc[mf][bq * 2 + 0], ah[mf], bl[0], bl[1]);
                    MMA16816(acc[mf][bq * 2 + 0], al[mf], bh[0], bh[1]);
                    MMA16816(acc[mf][bq * 2 + 1], ah[mf], bh[2], bh[3]);
                    MMA16816(acc[mf][bq * 2 + 1], ah[mf], bl[2], bl[3]);
                    MMA16816(acc[mf][bq * 2 + 1], al[mf], bh[2], bh[3]);
                }
            }
        }
        if (c < 5) {
            __syncthreads();
            load_chunk(c + 1);
            __syncthreads();
        }
    }

    // ---- epilogue: bias + store ----
    const int qrow = lane >> 2, qcol = (lane & 3) * 2;
    #pragma unroll
    for (int nf = 0; nf < 8; nf++) {
        int col = warp_n * 64 + nf * 8 + qcol;
        float b0 = __ldg(&bias[col]);
        float b1 = __ldg(&bias[col + 1]);
        #pragma unroll
        for (int mf = 0; mf < 2; mf++) {
            int row0 = rbase + warp_m * 32 + mf * 16 + qrow;
            if (row0 < NN)
                *(float2*)(out + (size_t)row0 * 128 + col) =
                    make_float2(acc[mf][nf][0] + b0, acc[mf][nf][1] + b1);
            int row1 = row0 + 8;
            if (row1 < NN)
                *(float2*)(out + (size_t)row1 * 128 + col) =
                    make_float2(acc[mf][nf][2] + b0, acc[mf][nf][3] + b1);
        }
    }
}

// ---------------- launch ------------------------------------------------------
extern "C" void kernel_launch(void* const* d_in, const int* in_sizes, int n_in,
                              void* d_out, int out_size) {
    const float* x        = (const float*)d_in[0];
    const int*   edge_src = (const int*)  d_in[1];
    const int*   edge_dst = (const int*)  d_in[2];
    const float* edge_val = (const float*)d_in[3];
    const float* W        = (const float*)d_in[4];
    const float* b        = (const float*)d_in[5];
    float* out = (float*)d_out;

    static bool attr_set = false;
    if (!attr_set) {
        cudaFuncSetAttribute(gemm_mma_kernel,
                             cudaFuncAttributeMaxDynamicSharedMemorySize,
                             SMEM_GEMM_BYTES);
        attr_set = true;
    }

    float *f1p, *f2p;
    cudaGetSymbolAddress((void**)&f1p, g_f1);
    cudaGetSymbolAddress((void**)&f2p, g_f2);

    // 1) W prep (tiny) + CSR build with parallel two-level scan
    wconv_kernel<<<(128 * KTOT + 255) / 256, 256>>>(W);
    zero_deg_kernel<<<(NN + 255) / 256, 256>>>();
    hist_kernel<<<(EE / 4 + 255) / 256, 256>>>(edge_src);
    scan_local_kernel<<<NB, 1024>>>();
    scan_tops_kernel<<<1, 128>>>();
    scan_add_kernel<<<(NN + 255) / 256, 256>>>();
    scatter_kernel<<<(EE / 4 + 255) / 256, 256>>>(edge_src, edge_dst, edge_val);

    // 2) Two SpMM hops
    int spmm_blocks = (NN + 7) / 8;
    spmm_kernel<<<spmm_blocks, 256>>>((const float4*)x,  (float4*)f1p);
    spmm_kernel<<<spmm_blocks, 256>>>((const float4*)f1p, (float4*)f2p);

    // 3) Tensor-core dense layer on [x | f1 | f2]
    gemm_mma_kernel<<<(NN + 127) / 128, 256, SMEM_GEMM_BYTES>>>(x, b, out);
}

// round 7
// speedup vs baseline: 1.6126x; 1.1373x over previous
#include <cuda_runtime.h>
#include <cuda_bf16.h>
#include <cuda_fp16.h>
#include <cstdint>

#define NN 100000
#define EE 1600000
#define D  128
#define KTOT 384
#define NB  ((NN + 1023) / 1024)   // 98 scan blocks

typedef unsigned long long ull;

// ---------------- scratch (static device globals; no allocation) -------------
__device__ __align__(16) __half g_xh[(size_t)NN * D];   // fp16 image of x
__device__ __align__(16) __half g_f1[(size_t)NN * D];   // hop-1 (fp16)
__device__ __align__(16) __half g_f2[(size_t)NN * D];   // hop-2 (fp16)
__device__ int   g_deg[NN];
__device__ int   g_cursor[NN];
__device__ int   g_rowptr[NN + 1];
__device__ int   g_blocksum[NB];
__device__ int   g_blockoff[NB];
__device__ int2  g_dstval[EE];          // packed (dst, val-bits)
// Pre-swizzled bf16 hi/lo images of W: 6 K-chunks of [128 n][64 k] bf16 (16 KB each)
__device__ __align__(16) unsigned char g_Wh[6 * 16384];
__device__ __align__(16) unsigned char g_Wl[6 * 16384];

// ---------------- PTX helpers -------------------------------------------------
__device__ __forceinline__ uint32_t smem_u32(const void* p) {
    uint32_t a;
    asm("{ .reg .u64 t; cvta.to.shared.u64 t, %1; cvt.u32.u64 %0, t; }" : "=r"(a) : "l"(p));
    return a;
}

#define LDSM4(R, A)                                                         \
    asm volatile("ldmatrix.sync.aligned.m8n8.x4.shared.b16 "                \
                 "{%0,%1,%2,%3}, [%4];"                                     \
                 : "=r"((R)[0]), "=r"((R)[1]), "=r"((R)[2]), "=r"((R)[3])   \
                 : "r"(A))

#define MMA16816(DD, AA, B0, B1)                                            \
    asm volatile("mma.sync.aligned.m16n8k16.row.col.f32.bf16.bf16.f32 "     \
                 "{%0,%1,%2,%3},{%4,%5,%6,%7},{%8,%9},{%0,%1,%2,%3};"       \
                 : "+f"((DD)[0]), "+f"((DD)[1]), "+f"((DD)[2]), "+f"((DD)[3]) \
                 : "r"((AA)[0]), "r"((AA)[1]), "r"((AA)[2]), "r"((AA)[3]),  \
                   "r"(B0), "r"(B1))

__device__ __forceinline__ uint32_t swz(uint32_t bo) {
    return bo ^ ((bo >> 3) & 0x70);
}

__device__ __forceinline__ int warp_incl_scan(int val, int lane) {
    #pragma unroll
    for (int off = 1; off < 32; off <<= 1) {
        int t = __shfl_up_sync(0xffffffffu, val, off);
        if (lane >= off) val += t;
    }
    return val;
}

__device__ __forceinline__ uint32_t pack_bf16(float a, float b) {
    __nv_bfloat16 ha = __float2bfloat16(a), hb = __float2bfloat16(b);
    return (uint32_t)__bfloat16_as_ushort(ha) |
           ((uint32_t)__bfloat16_as_ushort(hb) << 16);
}

// ---------------- x -> fp16 image ---------------------------------------------
__global__ void xconv_kernel(const float4* __restrict__ x4) {
    int i = blockIdx.x * blockDim.x + threadIdx.x;      // over NN*D/8
    if (i >= NN * D / 8) return;
    float4 a = __ldg(&x4[i * 2]);
    float4 b = __ldg(&x4[i * 2 + 1]);
    __half2 h0 = __float22half2_rn(make_float2(a.x, a.y));
    __half2 h1 = __float22half2_rn(make_float2(a.z, a.w));
    __half2 h2 = __float22half2_rn(make_float2(b.x, b.y));
    __half2 h3 = __float22half2_rn(make_float2(b.z, b.w));
    uint4 o;
    o.x = *(uint32_t*)&h0; o.y = *(uint32_t*)&h1;
    o.z = *(uint32_t*)&h2; o.w = *(uint32_t*)&h3;
    ((uint4*)g_xh)[i] = o;
}

// ---------------- CSR build ---------------------------------------------------
__global__ void zero_deg_kernel() {
    int i = blockIdx.x * blockDim.x + threadIdx.x;
    if (i < NN) g_deg[i] = 0;
}

__global__ void hist_kernel(const int* __restrict__ src) {
    int t = blockIdx.x * blockDim.x + threadIdx.x;   // 4 edges per thread
    int e = t * 4;
    if (e + 3 < EE) {
        int4 s = __ldg((const int4*)(src + e));
        atomicAdd(&g_deg[s.x], 1);
        atomicAdd(&g_deg[s.y], 1);
        atomicAdd(&g_deg[s.z], 1);
        atomicAdd(&g_deg[s.w], 1);
    } else {
        for (int q = e; q < EE; q++) atomicAdd(&g_deg[__ldg(src + q)], 1);
    }
}

__global__ __launch_bounds__(1024)
void scan_local_kernel() {
    __shared__ int warpsums[32];
    int tid = threadIdx.x, lane = tid & 31, wid = tid >> 5;
    int i = blockIdx.x * 1024 + tid;
    int v = (i < NN) ? g_deg[i] : 0;
    int val = warp_incl_scan(v, lane);
    if (lane == 31) warpsums[wid] = val;
    __syncthreads();
    if (wid == 0) warpsums[lane] = warp_incl_scan(warpsums[lane], lane);
    __syncthreads();
    int excl = val - v + (wid > 0 ? warpsums[wid - 1] : 0);
    if (i < NN) g_rowptr[i] = excl;
    if (tid == 0) g_blocksum[blockIdx.x] = warpsums[31];
}

__global__ __launch_bounds__(128)
void scan_tops_kernel() {
    __shared__ int ws[4];
    int tid = threadIdx.x, lane = tid & 31, wid = tid >> 5;
    int v = (tid < NB) ? g_blocksum[tid] : 0;
    int val = warp_incl_scan(v, lane);
    if (lane == 31) ws[wid] = val;
    __syncthreads();
    if (tid == 0) {
        int a = ws[0];
        ws[0] = 0;
        #pragma unroll
        for (int q = 1; q < 4; q++) { int t = ws[q]; ws[q] = a; a += t; }
    }
    __syncthreads();
    if (tid < NB) g_blockoff[tid] = val - v + ws[wid];
}

__global__ void scan_add_kernel() {
    int i = blockIdx.x * blockDim.x + threadIdx.x;
    if (i < NN) {
        int r = g_rowptr[i] + g_blockoff[i >> 10];
        g_rowptr[i] = r;
        g_cursor[i] = r;
    }
    if (i == 0) g_rowptr[NN] = EE;
}

__global__ void scatter_kernel(const int* __restrict__ src,
                               const int* __restrict__ dst,
                               const float* __restrict__ val) {
    int t = blockIdx.x * blockDim.x + threadIdx.x;
    int e = t * 4;
    if (e + 3 < EE) {
        int4   s = __ldg((const int4*)(src + e));
        int4   d = __ldg((const int4*)(dst + e));
        float4 v = __ldg((const float4*)(val + e));
        int p0 = atomicAdd(&g_cursor[s.x], 1);
        int p1 = atomicAdd(&g_cursor[s.y], 1);
        int p2 = atomicAdd(&g_cursor[s.z], 1);
        int p3 = atomicAdd(&g_cursor[s.w], 1);
        g_dstval[p0] = make_int2(d.x, __float_as_int(v.x));
        g_dstval[p1] = make_int2(d.y, __float_as_int(v.y));
        g_dstval[p2] = make_int2(d.z, __float_as_int(v.z));
        g_dstval[p3] = make_int2(d.w, __float_as_int(v.w));
    } else {
        for (int q = e; q < EE; q++) {
            int dd = __ldg(dst + q);
            float vv = __ldg(val + q);
            int pos = atomicAdd(&g_cursor[__ldg(src + q)], 1);
            g_dstval[pos] = make_int2(dd, __float_as_int(vv));
        }
    }
}

// ---------------- SpMM (fp16 rows): one warp per row -------------------------
// Row = 128 halves = 32 uint2; lane handles 4 features. fp32 accumulation.
__global__ __launch_bounds__(256)
void spmm_kernel(const uint2* __restrict__ fin, uint2* __restrict__ fout) {
    int warp = (blockIdx.x * blockDim.x + threadIdx.x) >> 5;
    int lane = threadIdx.x & 31;
    if (warp >= NN) return;
    int beg = __ldg(&g_rowptr[warp]);
    int end = __ldg(&g_rowptr[warp + 1]);

    float4 acc = make_float4(0.f, 0.f, 0.f, 0.f);
    int j = beg;
    for (; j + 4 <= end; j += 4) {
        int2 m0 = __ldg(&g_dstval[j]);
        int2 m1 = __ldg(&g_dstval[j + 1]);
        int2 m2 = __ldg(&g_dstval[j + 2]);
        int2 m3 = __ldg(&g_dstval[j + 3]);
        uint2 a0 = __ldg(&fin[(size_t)m0.x * 32 + lane]);
        uint2 a1 = __ldg(&fin[(size_t)m1.x * 32 + lane]);
        uint2 a2 = __ldg(&fin[(size_t)m2.x * 32 + lane]);
        uint2 a3 = __ldg(&fin[(size_t)m3.x * 32 + lane]);
        float v0 = __int_as_float(m0.y), v1 = __int_as_float(m1.y);
        float v2 = __int_as_float(m2.y), v3 = __int_as_float(m3.y);
        #pragma unroll
        for (int p = 0; p < 1; p++) {   // unrolled manually below
            float2 f0a = __half22float2(*(__half2*)&a0.x);
            float2 f0b = __half22float2(*(__half2*)&a0.y);
            float2 f1a = __half22float2(*(__half2*)&a1.x);
            float2 f1b = __half22float2(*(__half2*)&a1.y);
            float2 f2a = __half22float2(*(__half2*)&a2.x);
            float2 f2b = __half22float2(*(__half2*)&a2.y);
            float2 f3a = __half22float2(*(__half2*)&a3.x);
            float2 f3b = __half22float2(*(__half2*)&a3.y);
            acc.x = fmaf(v0, f0a.x, fmaf(v1, f1a.x, fmaf(v2, f2a.x, fmaf(v3, f3a.x, acc.x))));
            acc.y = fmaf(v0, f0a.y, fmaf(v1, f1a.y, fmaf(v2, f2a.y, fmaf(v3, f3a.y, acc.y))));
            acc.z = fmaf(v0, f0b.x, fmaf(v1, f1b.x, fmaf(v2, f2b.x, fmaf(v3, f3b.x, acc.z))));
            acc.w = fmaf(v0, f0b.y, fmaf(v1, f1b.y, fmaf(v2, f2b.y, fmaf(v3, f3b.y, acc.w))));
        }
    }
    for (; j < end; j++) {
        int2 m = __ldg(&g_dstval[j]);
        float v = __int_as_float(m.y);
        uint2 a = __ldg(&fin[(size_t)m.x * 32 + lane]);
        float2 fa = __half22float2(*(__half2*)&a.x);
        float2 fb = __half22float2(*(__half2*)&a.y);
        acc.x = fmaf(v, fa.x, acc.x);
        acc.y = fmaf(v, fa.y, acc.y);
        acc.z = fmaf(v, fb.x, acc.z);
        acc.w = fmaf(v, fb.y, acc.w);
    }
    __half2 o0 = __float22half2_rn(make_float2(acc.x, acc.y));
    __half2 o1 = __float22half2_rn(make_float2(acc.z, acc.w));
    uint2 o;
    o.x = *(uint32_t*)&o0; o.y = *(uint32_t*)&o1;
    fout[(size_t)warp * 32 + lane] = o;
}

// ---------------- W -> bf16 hi/lo, pre-swizzled SW128 chunks ------------------
__global__ void wconv_kernel(const float* __restrict__ W) {
    int i = blockIdx.x * blockDim.x + threadIdx.x;   // over 128 * 384
    if (i >= 128 * KTOT) return;
    int n = i / KTOT, k = i % KTOT;
    float v = W[i];
    __nv_bfloat16 h = __float2bfloat16(v);
    float rh = __bfloat162float(h);
    __nv_bfloat16 l = __float2bfloat16(v - rh);
    int c = k >> 6, kk = k & 63;
    uint32_t sw = swz((uint32_t)n * 128 + kk * 2);
    *(__nv_bfloat16*)(g_Wh + c * 16384 + sw) = h;
    *(__nv_bfloat16*)(g_Wl + c * 16384 + sw) = l;
}

// ---------------- mma.sync GEMM: out = [x|f1|f2] @ W^T + b --------------------
// CTA: 128 rows x 128 cols, K=384 in six 64-chunks, bf16 split-2 (3 products).
// Chunks 0-1: x fp32 -> split. Chunks 2-5: f1/f2 fp16 -> exact bf16 hi/lo split.
#define SMEM_GEMM_BYTES (1024 + 4 * 16384)

__global__ __launch_bounds__(256, 2)
void gemm_mma_kernel(const float* __restrict__ x,
                     const float* __restrict__ bias,
                     float* __restrict__ out) {
    extern __shared__ unsigned char dsm[];
    const int tid  = threadIdx.x;
    const int lane = tid & 31;
    const int wid  = tid >> 5;
    const int warp_m = wid & 3;
    const int warp_n = wid >> 2;
    const int rbase  = blockIdx.x * 128;

    uint32_t sb0  = smem_u32(dsm);
    uint32_t base = (sb0 + 1023) & ~1023u;
    unsigned char* gp = dsm + (base - sb0);
    const uint32_t Ah = base, Al = base + 16384, Bh = base + 32768, Bl = base + 49152;

    auto load_chunk = [&](int c) {
        unsigned char* pAh = gp;
        unsigned char* pAl = gp + 16384;
        if (c < 2) {
            const float4* s4 = (const float4*)x;
            int koff = c * 16;
            #pragma unroll
            for (int it = 0; it < 8; it++) {
                int idx = tid + it * 256;
                int row = idx >> 4, c4 = idx & 15;
                int grow = rbase + row;
                float4 v = make_float4(0.f, 0.f, 0.f, 0.f);
                if (grow < NN) v = s4[(size_t)grow * 32 + koff + c4];
                __nv_bfloat16 h0 = __float2bfloat16(v.x), h1 = __float2bfloat16(v.y);
                __nv_bfloat16 h2 = __float2bfloat16(v.z), h3 = __float2bfloat16(v.w);
                float r0 = v.x - __bfloat162float(h0);
                float r1 = v.y - __bfloat162float(h1);
                float r2 = v.z - __bfloat162float(h2);
                float r3 = v.w - __bfloat162float(h3);
                uint32_t hw0 = (uint32_t)__bfloat16_as_ushort(h0) |
                               ((uint32_t)__bfloat16_as_ushort(h1) << 16);
                uint32_t hw1 = (uint32_t)__bfloat16_as_ushort(h2) |
                               ((uint32_t)__bfloat16_as_ushort(h3) << 16);
                uint32_t lw0 = pack_bf16(r0, r1);
                uint32_t lw1 = pack_bf16(r2, r3);
                uint32_t sw = swz((uint32_t)row * 128 + c4 * 8);
                *(uint2*)(pAh + sw) = make_uint2(hw0, hw1);
                *(uint2*)(pAl + sw) = make_uint2(lw0, lw1);
            }
        } else {
            const uint2* s2 = (const uint2*)((c < 4) ? g_f1 : g_f2);
            int koff = (c & 1) * 16;                  // uint2 offset within row
            #pragma unroll
            for (int it = 0; it < 8; it++) {
                int idx = tid + it * 256;
                int row = idx >> 4, c4 = idx & 15;
                int grow = rbase + row;
                uint2 hv = make_uint2(0u, 0u);
                if (grow < NN) hv = s2[(size_t)grow * 32 + koff + c4];
                float2 fa = __half22float2(*(__half2*)&hv.x);
                float2 fb = __half22float2(*(__half2*)&hv.y);
                __nv_bfloat16 h0 = __float2bfloat16(fa.x), h1 = __float2bfloat16(fa.y);
                __nv_bfloat16 h2 = __float2bfloat16(fb.x), h3 = __float2bfloat16(fb.y);
                float r0 = fa.x - __bfloat162float(h0);
                float r1 = fa.y - __bfloat162float(h1);
                float r2 = fb.x - __bfloat162float(h2);
                float r3 = fb.y - __bfloat162float(h3);
                uint32_t hw0 = (uint32_t)__bfloat16_as_ushort(h0) |
                               ((uint32_t)__bfloat16_as_ushort(h1) << 16);
                uint32_t hw1 = (uint32_t)__bfloat16_as_ushort(h2) |
                               ((uint32_t)__bfloat16_as_ushort(h3) << 16);
                uint32_t lw0 = pack_bf16(r0, r1);
                uint32_t lw1 = pack_bf16(r2, r3);
                uint32_t sw = swz((uint32_t)row * 128 + c4 * 8);
                *(uint2*)(pAh + sw) = make_uint2(hw0, hw1);
                *(uint2*)(pAl + sw) = make_uint2(lw0, lw1);
            }
        }
        const uint4* wh = (const uint4*)(g_Wh + c * 16384);
        const uint4* wl = (const uint4*)(g_Wl + c * 16384);
        uint4* pBh = (uint4*)(gp + 32768);
        uint4* pBl = (uint4*)(gp + 49152);
        #pragma unroll
        for (int it = 0; it < 4; it++) {
            int i = tid + it * 256;
            pBh[i] = wh[i];
            pBl[i] = wl[i];
        }
    };

    float acc[2][8][4];
    #pragma unroll
    for (int mf = 0; mf < 2; mf++)
        #pragma unroll
        for (int nf = 0; nf < 8; nf++)
            #pragma unroll
            for (int q = 0; q < 4; q++) acc[mf][nf][q] = 0.f;

    const int g = lane >> 3, r = lane & 7;
    const int a_row_off = r + (g & 1) * 8;
    const int a_k_off   = (g >> 1) * 8;
    const int b_n_off   = r + (g >> 1) * 8;
    const int b_k_off   = (g & 1) * 8;

    load_chunk(0);
    __syncthreads();

    for (int c = 0; c < 6; c++) {
        #pragma unroll
        for (int ks = 0; ks < 4; ks++) {
            const int k0 = ks * 16;
            uint32_t ah[2][4], al[2][4];
            #pragma unroll
            for (int mf = 0; mf < 2; mf++) {
                uint32_t sw = swz((uint32_t)(warp_m * 32 + mf * 16 + a_row_off) * 128
                                  + (k0 + a_k_off) * 2);
                LDSM4(ah[mf], Ah + sw);
                LDSM4(al[mf], Al + sw);
            }
            #pragma unroll
            for (int bq = 0; bq < 4; bq++) {
                uint32_t sw = swz((uint32_t)(warp_n * 64 + bq * 16 + b_n_off) * 128
                                  + (k0 + b_k_off) * 2);
                uint32_t bh[4], bl[4];
                LDSM4(bh, Bh + sw);
                LDSM4(bl, Bl + sw);
                #pragma unroll
                for (int mf = 0; mf < 2; mf++) {
                    MMA16816(acc[mf][bq * 2 + 0], ah[mf], bh[0], bh[1]);
                    MMA16816(acc[mf][bq * 2 + 0], ah[mf], bl[0], bl[1]);
                    MMA16816(acc[mf][bq * 2 + 0], al[mf], bh[0], bh[1]);
                    MMA16816(acc[mf][bq * 2 + 1], ah[mf], bh[2], bh[3]);
                    MMA16816(acc[mf][bq * 2 + 1], ah[mf], bl[2], bl[3]);
                    MMA16816(acc[mf][bq * 2 + 1], al[mf], bh[2], bh[3]);
                }
            }
        }
        if (c < 5) {
            __syncthreads();
            load_chunk(c + 1);
            __syncthreads();
        }
    }

    // ---- epilogue: bias + store ----
    const int qrow = lane >> 2, qcol = (lane & 3) * 2;
    #pragma unroll
    for (int nf = 0; nf < 8; nf++) {
        int col = warp_n * 64 + nf * 8 + qcol;
        float b0 = __ldg(&bias[col]);
        float b1 = __ldg(&bias[col + 1]);
        #pragma unroll
        for (int mf = 0; mf < 2; mf++) {
            int row0 = rbase + warp_m * 32 + mf * 16 + qrow;
            if (row0 < NN)
                *(float2*)(out + (size_t)row0 * 128 + col) =
                    make_float2(acc[mf][nf][0] + b0, acc[mf][nf][1] + b1);
            int row1 = row0 + 8;
            if (row1 < NN)
                *(float2*)(out + (size_t)row1 * 128 + col) =
                    make_float2(acc[mf][nf][2] + b0, acc[mf][nf][3] + b1);
        }
    }
}

// ---------------- launch ------------------------------------------------------
extern "C" void kernel_launch(void* const* d_in, const int* in_sizes, int n_in,
                              void* d_out, int out_size) {
    const float* x        = (const float*)d_in[0];
    const int*   edge_src = (const int*)  d_in[1];
    const int*   edge_dst = (const int*)  d_in[2];
    const float* edge_val = (const float*)d_in[3];
    const float* W        = (const float*)d_in[4];
    const float* b        = (const float*)d_in[5];
    float* out = (float*)d_out;

    static bool attr_set = false;
    if (!attr_set) {
        cudaFuncSetAttribute(gemm_mma_kernel,
                             cudaFuncAttributeMaxDynamicSharedMemorySize,
                             SMEM_GEMM_BYTES);
        attr_set = true;
    }

    uint2 *xhp, *f1p, *f2p;
    cudaGetSymbolAddress((void**)&xhp, g_xh);
    cudaGetSymbolAddress((void**)&f1p, g_f1);
    cudaGetSymbolAddress((void**)&f2p, g_f2);

    // 1) Prep: W split, x fp16 image, CSR build with parallel scan
    wconv_kernel<<<(128 * KTOT + 255) / 256, 256>>>(W);
    xconv_kernel<<<(NN * D / 8 + 255) / 256, 256>>>((const float4*)x);
    zero_deg_kernel<<<(NN + 255) / 256, 256>>>();
    hist_kernel<<<(EE / 4 + 255) / 256, 256>>>(edge_src);
    scan_local_kernel<<<NB, 1024>>>();
    scan_tops_kernel<<<1, 128>>>();
    scan_add_kernel<<<(NN + 255) / 256, 256>>>();
    scatter_kernel<<<(EE / 4 + 255) / 256, 256>>>(edge_src, edge_dst, edge_val);

    // 2) Two SpMM hops (fp16 gather, fp32 accumulate)
    int spmm_blocks = (NN + 7) / 8;
    spmm_kernel<<<spmm_blocks, 256>>>(xhp, f1p);
    spmm_kernel<<<spmm_blocks, 256>>>(f1p, f2p);

    // 3) Tensor-core dense layer on [x | f1 | f2]
    gemm_mma_kernel<<<(NN + 127) / 128, 256, SMEM_GEMM_BYTES>>>(x, b, out);
}

// round 8
// speedup vs baseline: 1.7540x; 1.0877x over previous
#include <cuda_runtime.h>
#include <cuda_bf16.h>
#include <cuda_fp16.h>
#include <cstdint>

#define NN 100000
#define EE 1600000
#define D  128
#define KTOT 384
#define NB  ((NN + 1023) / 1024)   // 98 scan blocks

typedef unsigned long long ull;

// ---------------- scratch (static device globals; no allocation) -------------
__device__ __align__(16) __half g_xh[(size_t)NN * D];   // fp16 image of x
__device__ __align__(16) __half g_f1[(size_t)NN * D];   // hop-1 (fp16)
__device__ __align__(16) __half g_f2[(size_t)NN * D];   // hop-2 (fp16)
__device__ int   g_deg[NN];
__device__ int   g_cursor[NN];
__device__ int   g_rowptr[NN + 1];
__device__ int   g_blocksum[NB];
__device__ int   g_blockoff[NB];
__device__ int2  g_dstval[EE];          // packed (dst, val-bits)
// Pre-swizzled fp16 hi/lo images of W: 6 K-chunks of [128 n][64 k] fp16 (16 KB each)
__device__ __align__(16) unsigned char g_Wh[6 * 16384];
__device__ __align__(16) unsigned char g_Wl[6 * 16384];

// ---------------- PTX helpers -------------------------------------------------
__device__ __forceinline__ uint32_t smem_u32(const void* p) {
    uint32_t a;
    asm("{ .reg .u64 t; cvta.to.shared.u64 t, %1; cvt.u32.u64 %0, t; }" : "=r"(a) : "l"(p));
    return a;
}

#define LDSM4(R, A)                                                         \
    asm volatile("ldmatrix.sync.aligned.m8n8.x4.shared.b16 "                \
                 "{%0,%1,%2,%3}, [%4];"                                     \
                 : "=r"((R)[0]), "=r"((R)[1]), "=r"((R)[2]), "=r"((R)[3])   \
                 : "r"(A))

#define MMAF16(DD, AA, B0, B1)                                              \
    asm volatile("mma.sync.aligned.m16n8k16.row.col.f32.f16.f16.f32 "       \
                 "{%0,%1,%2,%3},{%4,%5,%6,%7},{%8,%9},{%0,%1,%2,%3};"       \
                 : "+f"((DD)[0]), "+f"((DD)[1]), "+f"((DD)[2]), "+f"((DD)[3]) \
                 : "r"((AA)[0]), "r"((AA)[1]), "r"((AA)[2]), "r"((AA)[3]),  \
                   "r"(B0), "r"(B1))

__device__ __forceinline__ uint32_t swz(uint32_t bo) {
    return bo ^ ((bo >> 3) & 0x70);
}

__device__ __forceinline__ int warp_incl_scan(int val, int lane) {
    #pragma unroll
    for (int off = 1; off < 32; off <<= 1) {
        int t = __shfl_up_sync(0xffffffffu, val, off);
        if (lane >= off) val += t;
    }
    return val;
}

// ---------------- x -> fp16 image ---------------------------------------------
__global__ void xconv_kernel(const float4* __restrict__ x4) {
    int i = blockIdx.x * blockDim.x + threadIdx.x;      // over NN*D/8
    if (i >= NN * D / 8) return;
    float4 a = __ldg(&x4[i * 2]);
    float4 b = __ldg(&x4[i * 2 + 1]);
    __half2 h0 = __float22half2_rn(make_float2(a.x, a.y));
    __half2 h1 = __float22half2_rn(make_float2(a.z, a.w));
    __half2 h2 = __float22half2_rn(make_float2(b.x, b.y));
    __half2 h3 = __float22half2_rn(make_float2(b.z, b.w));
    uint4 o;
    o.x = *(uint32_t*)&h0; o.y = *(uint32_t*)&h1;
    o.z = *(uint32_t*)&h2; o.w = *(uint32_t*)&h3;
    ((uint4*)g_xh)[i] = o;
}

// ---------------- CSR build ---------------------------------------------------
__global__ void zero_deg_kernel() {
    int i = blockIdx.x * blockDim.x + threadIdx.x;
    if (i < NN) g_deg[i] = 0;
}

__global__ void hist_kernel(const int* __restrict__ src) {
    int t = blockIdx.x * blockDim.x + threadIdx.x;   // 4 edges per thread
    int e = t * 4;
    if (e + 3 < EE) {
        int4 s = __ldg((const int4*)(src + e));
        atomicAdd(&g_deg[s.x], 1);
        atomicAdd(&g_deg[s.y], 1);
        atomicAdd(&g_deg[s.z], 1);
        atomicAdd(&g_deg[s.w], 1);
    } else {
        for (int q = e; q < EE; q++) atomicAdd(&g_deg[__ldg(src + q)], 1);
    }
}

__global__ __launch_bounds__(1024)
void scan_local_kernel() {
    __shared__ int warpsums[32];
    int tid = threadIdx.x, lane = tid & 31, wid = tid >> 5;
    int i = blockIdx.x * 1024 + tid;
    int v = (i < NN) ? g_deg[i] : 0;
    int val = warp_incl_scan(v, lane);
    if (lane == 31) warpsums[wid] = val;
    __syncthreads();
    if (wid == 0) warpsums[lane] = warp_incl_scan(warpsums[lane], lane);
    __syncthreads();
    int excl = val - v + (wid > 0 ? warpsums[wid - 1] : 0);
    if (i < NN) g_rowptr[i] = excl;
    if (tid == 0) g_blocksum[blockIdx.x] = warpsums[31];
}

__global__ __launch_bounds__(128)
void scan_tops_kernel() {
    __shared__ int ws[4];
    int tid = threadIdx.x, lane = tid & 31, wid = tid >> 5;
    int v = (tid < NB) ? g_blocksum[tid] : 0;
    int val = warp_incl_scan(v, lane);
    if (lane == 31) ws[wid] = val;
    __syncthreads();
    if (tid == 0) {
        int a = ws[0];
        ws[0] = 0;
        #pragma unroll
        for (int q = 1; q < 4; q++) { int t = ws[q]; ws[q] = a; a += t; }
    }
    __syncthreads();
    if (tid < NB) g_blockoff[tid] = val - v + ws[wid];
}

__global__ void scan_add_kernel() {
    int i = blockIdx.x * blockDim.x + threadIdx.x;
    if (i < NN) {
        int r = g_rowptr[i] + g_blockoff[i >> 10];
        g_rowptr[i] = r;
        g_cursor[i] = r;
    }
    if (i == 0) g_rowptr[NN] = EE;
}

__global__ void scatter_kernel(const int* __restrict__ src,
                               const int* __restrict__ dst,
                               const float* __restrict__ val) {
    int t = blockIdx.x * blockDim.x + threadIdx.x;
    int e = t * 4;
    if (e + 3 < EE) {
        int4   s = __ldg((const int4*)(src + e));
        int4   d = __ldg((const int4*)(dst + e));
        float4 v = __ldg((const float4*)(val + e));
        int p0 = atomicAdd(&g_cursor[s.x], 1);
        int p1 = atomicAdd(&g_cursor[s.y], 1);
        int p2 = atomicAdd(&g_cursor[s.z], 1);
        int p3 = atomicAdd(&g_cursor[s.w], 1);
        g_dstval[p0] = make_int2(d.x, __float_as_int(v.x));
        g_dstval[p1] = make_int2(d.y, __float_as_int(v.y));
        g_dstval[p2] = make_int2(d.z, __float_as_int(v.z));
        g_dstval[p3] = make_int2(d.w, __float_as_int(v.w));
    } else {
        for (int q = e; q < EE; q++) {
            int dd = __ldg(dst + q);
            float vv = __ldg(val + q);
            int pos = atomicAdd(&g_cursor[__ldg(src + q)], 1);
            g_dstval[pos] = make_int2(dd, __float_as_int(vv));
        }
    }
}

// ---------------- SpMM (fp16 rows): one warp per row, 8-deep unroll ----------
__global__ __launch_bounds__(256)
void spmm_kernel(const uint2* __restrict__ fin, uint2* __restrict__ fout) {
    int warp = (blockIdx.x * blockDim.x + threadIdx.x) >> 5;
    int lane = threadIdx.x & 31;
    if (warp >= NN) return;
    int beg = __ldg(&g_rowptr[warp]);
    int end = __ldg(&g_rowptr[warp + 1]);

    float4 acc = make_float4(0.f, 0.f, 0.f, 0.f);
    int j = beg;
    for (; j + 8 <= end; j += 8) {
        int2 m[8];
        uint2 a[8];
        #pragma unroll
        for (int q = 0; q < 8; q++) m[q] = __ldg(&g_dstval[j + q]);
        #pragma unroll
        for (int q = 0; q < 8; q++) a[q] = __ldg(&fin[(size_t)m[q].x * 32 + lane]);
        #pragma unroll
        for (int q = 0; q < 8; q++) {
            float v = __int_as_float(m[q].y);
            float2 fa = __half22float2(*(__half2*)&a[q].x);
            float2 fb = __half22float2(*(__half2*)&a[q].y);
            acc.x = fmaf(v, fa.x, acc.x);
            acc.y = fmaf(v, fa.y, acc.y);
            acc.z = fmaf(v, fb.x, acc.z);
            acc.w = fmaf(v, fb.y, acc.w);
        }
    }
    for (; j < end; j++) {
        int2 m = __ldg(&g_dstval[j]);
        float v = __int_as_float(m.y);
        uint2 a = __ldg(&fin[(size_t)m.x * 32 + lane]);
        float2 fa = __half22float2(*(__half2*)&a.x);
        float2 fb = __half22float2(*(__half2*)&a.y);
        acc.x = fmaf(v, fa.x, acc.x);
        acc.y = fmaf(v, fa.y, acc.y);
        acc.z = fmaf(v, fb.x, acc.z);
        acc.w = fmaf(v, fb.y, acc.w);
    }
    __half2 o0 = __float22half2_rn(make_float2(acc.x, acc.y));
    __half2 o1 = __float22half2_rn(make_float2(acc.z, acc.w));
    uint2 o;
    o.x = *(uint32_t*)&o0; o.y = *(uint32_t*)&o1;
    fout[(size_t)warp * 32 + lane] = o;
}

// ---------------- W -> fp16 hi/lo, pre-swizzled SW128 chunks ------------------
__global__ void wconv_kernel(const float* __restrict__ W) {
    int i = blockIdx.x * blockDim.x + threadIdx.x;   // over 128 * 384
    if (i >= 128 * KTOT) return;
    int n = i / KTOT, k = i % KTOT;
    float v = W[i];
    __half h = __float2half_rn(v);
    __half l = __float2half_rn(v - __half2float(h));
    int c = k >> 6, kk = k & 63;
    uint32_t sw = swz((uint32_t)n * 128 + kk * 2);
    *(__half*)(g_Wh + c * 16384 + sw) = h;
    *(__half*)(g_Wl + c * 16384 + sw) = l;
}

// ---------------- mma.sync GEMM: out = [xh|f1|f2] @ W^T + b -------------------
// CTA: 128 rows x 128 cols, K=384 in six 64-chunks. A fp16 exact (1 operand),
// W fp16 split-2 -> 2 MMA products. 8 warps 4(m)x2(n), warp tile 32x64.
#define SMEM_GEMM_BYTES (1024 + 3 * 16384)

__global__ __launch_bounds__(256, 2)
void gemm_mma_kernel(const float* __restrict__ bias,
                     float* __restrict__ out) {
    extern __shared__ unsigned char dsm[];
    const int tid  = threadIdx.x;
    const int lane = tid & 31;
    const int wid  = tid >> 5;
    const int warp_m = wid & 3;
    const int warp_n = wid >> 2;
    const int rbase  = blockIdx.x * 128;

    uint32_t sb0  = smem_u32(dsm);
    uint32_t base = (sb0 + 1023) & ~1023u;
    unsigned char* gp = dsm + (base - sb0);
    const uint32_t At = base, Bh = base + 16384, Bl = base + 32768;

    auto load_chunk = [&](int c) {
        const uint4* fsrc = (const uint4*)((c < 2) ? g_xh : (c < 4) ? g_f1 : g_f2);
        int koff = (c & 1) * 8;                       // uint4 (16B) offset in row
        #pragma unroll
        for (int it = 0; it < 4; it++) {
            int idx = tid + it * 256;                 // 1024 x 16B
            int row = idx >> 3, c8 = idx & 7;
            int grow = rbase + row;
            uint4 v = make_uint4(0u, 0u, 0u, 0u);
            if (grow < NN) v = fsrc[(size_t)grow * 16 + koff + c8];
            *(uint4*)(gp + swz((uint32_t)row * 128 + c8 * 16)) = v;
        }
        const uint4* wh = (const uint4*)(g_Wh + c * 16384);
        const uint4* wl = (const uint4*)(g_Wl + c * 16384);
        uint4* pBh = (uint4*)(gp + 16384);
        uint4* pBl = (uint4*)(gp + 32768);
        #pragma unroll
        for (int it = 0; it < 4; it++) {
            int i = tid + it * 256;
            pBh[i] = wh[i];
            pBl[i] = wl[i];
        }
    };

    float acc[2][8][4];
    #pragma unroll
    for (int mf = 0; mf < 2; mf++)
        #pragma unroll
        for (int nf = 0; nf < 8; nf++)
            #pragma unroll
            for (int q = 0; q < 4; q++) acc[mf][nf][q] = 0.f;

    const int g = lane >> 3, r = lane & 7;
    const int a_row_off = r + (g & 1) * 8;
    const int a_k_off   = (g >> 1) * 8;
    const int b_n_off   = r + (g >> 1) * 8;
    const int b_k_off   = (g & 1) * 8;

    load_chunk(0);
    __syncthreads();

    for (int c = 0; c < 6; c++) {
        #pragma unroll
        for (int ks = 0; ks < 4; ks++) {
            const int k0 = ks * 16;
            uint32_t ah[2][4];
            #pragma unroll
            for (int mf = 0; mf < 2; mf++) {
                uint32_t sw = swz((uint32_t)(warp_m * 32 + mf * 16 + a_row_off) * 128
                                  + (k0 + a_k_off) * 2);
                LDSM4(ah[mf], At + sw);
            }
            #pragma unroll
            for (int bq = 0; bq < 4; bq++) {
                uint32_t sw = swz((uint32_t)(warp_n * 64 + bq * 16 + b_n_off) * 128
                                  + (k0 + b_k_off) * 2);
                uint32_t bh[4], bl[4];
                LDSM4(bh, Bh + sw);
                LDSM4(bl, Bl + sw);
                #pragma unroll
                for (int mf = 0; mf < 2; mf++) {
                    MMAF16(acc[mf][bq * 2 + 0], ah[mf], bh[0], bh[1]);
                    MMAF16(acc[mf][bq * 2 + 0], ah[mf], bl[0], bl[1]);
                    MMAF16(acc[mf][bq * 2 + 1], ah[mf], bh[2], bh[3]);
                    MMAF16(acc[mf][bq * 2 + 1], ah[mf], bl[2], bl[3]);
                }
            }
        }
        if (c < 5) {
            __syncthreads();
            load_chunk(c + 1);
            __syncthreads();
        }
    }

    // ---- epilogue: bias + store ----
    const int qrow = lane >> 2, qcol = (lane & 3) * 2;
    #pragma unroll
    for (int nf = 0; nf < 8; nf++) {
        int col = warp_n * 64 + nf * 8 + qcol;
        float b0 = __ldg(&bias[col]);
        float b1 = __ldg(&bias[col + 1]);
        #pragma unroll
        for (int mf = 0; mf < 2; mf++) {
            int row0 = rbase + warp_m * 32 + mf * 16 + qrow;
            if (row0 < NN)
                *(float2*)(out + (size_t)row0 * 128 + col) =
                    make_float2(acc[mf][nf][0] + b0, acc[mf][nf][1] + b1);
            int row1 = row0 + 8;
            if (row1 < NN)
                *(float2*)(out + (size_t)row1 * 128 + col) =
                    make_float2(acc[mf][nf][2] + b0, acc[mf][nf][3] + b1);
        }
    }
}

// ---------------- launch ------------------------------------------------------
extern "C" void kernel_launch(void* const* d_in, const int* in_sizes, int n_in,
                              void* d_out, int out_size) {
    const float* x        = (const float*)d_in[0];
    const int*   edge_src = (const int*)  d_in[1];
    const int*   edge_dst = (const int*)  d_in[2];
    const float* edge_val = (const float*)d_in[3];
    const float* W        = (const float*)d_in[4];
    const float* b        = (const float*)d_in[5];
    float* out = (float*)d_out;

    static bool attr_set = false;
    if (!attr_set) {
        cudaFuncSetAttribute(gemm_mma_kernel,
                             cudaFuncAttributeMaxDynamicSharedMemorySize,
                             SMEM_GEMM_BYTES);
        attr_set = true;
    }

    uint2 *xhp, *f1p, *f2p;
    cudaGetSymbolAddress((void**)&xhp, g_xh);
    cudaGetSymbolAddress((void**)&f1p, g_f1);
    cudaGetSymbolAddress((void**)&f2p, g_f2);

    // 1) Prep: W split, x fp16 image, CSR build with parallel scan
    wconv_kernel<<<(128 * KTOT + 255) / 256, 256>>>(W);
    xconv_kernel<<<(NN * D / 8 + 255) / 256, 256>>>((const float4*)x);
    zero_deg_kernel<<<(NN + 255) / 256, 256>>>();
    hist_kernel<<<(EE / 4 + 255) / 256, 256>>>(edge_src);
    scan_local_kernel<<<NB, 1024>>>();
    scan_tops_kernel<<<1, 128>>>();
    scan_add_kernel<<<(NN + 255) / 256, 256>>>();
    scatter_kernel<<<(EE / 4 + 255) / 256, 256>>>(edge_src, edge_dst, edge_val);

    // 2) Two SpMM hops (fp16 gather, fp32 accumulate)
    int spmm_blocks = (NN + 7) / 8;
    spmm_kernel<<<spmm_blocks, 256>>>(xhp, f1p);
    spmm_kernel<<<spmm_blocks, 256>>>(f1p, f2p);

    // 3) Tensor-core dense layer on [xh | f1 | f2]
    gemm_mma_kernel<<<(NN + 127) / 128, 256, SMEM_GEMM_BYTES>>>(b, out);
}

// round 9
// speedup vs baseline: 1.9936x; 1.1366x over previous
#include <cuda_runtime.h>
#include <cuda_bf16.h>
#include <cuda_fp16.h>
#include <cstdint>

#define NN 100000
#define EE 1600000
#define D  128
#define KTOT 384
#define NB  ((NN + 1023) / 1024)   // 98 scan blocks

typedef unsigned long long ull;

// ---------------- scratch (static device globals; no allocation) -------------
__device__ __align__(16) __half g_xh[(size_t)NN * D];   // fp16 image of x
__device__ __align__(16) __half g_f1[(size_t)NN * D];   // hop-1 (fp16)
__device__ __align__(16) __half g_f2[(size_t)NN * D];   // hop-2 (fp16)
__device__ int   g_deg[NN];
__device__ int   g_cursor[NN];
__device__ int   g_rowptr[NN + 1];
__device__ int   g_blocksum[NB];
__device__ int   g_blockoff[NB];
__device__ int2  g_dstval[EE];          // packed (dst, val-bits)
// Pre-swizzled fp16 image of W: 6 K-chunks of [128 n][64 k] fp16 (16 KB each)
__device__ __align__(16) unsigned char g_Wh[6 * 16384];

// ---------------- PTX helpers -------------------------------------------------
__device__ __forceinline__ uint32_t smem_u32(const void* p) {
    uint32_t a;
    asm("{ .reg .u64 t; cvta.to.shared.u64 t, %1; cvt.u32.u64 %0, t; }" : "=r"(a) : "l"(p));
    return a;
}

#define LDSM4(R, A)                                                         \
    asm volatile("ldmatrix.sync.aligned.m8n8.x4.shared.b16 "                \
                 "{%0,%1,%2,%3}, [%4];"                                     \
                 : "=r"((R)[0]), "=r"((R)[1]), "=r"((R)[2]), "=r"((R)[3])   \
                 : "r"(A))

#define MMAF16(DD, AA, B0, B1)                                              \
    asm volatile("mma.sync.aligned.m16n8k16.row.col.f32.f16.f16.f32 "       \
                 "{%0,%1,%2,%3},{%4,%5,%6,%7},{%8,%9},{%0,%1,%2,%3};"       \
                 : "+f"((DD)[0]), "+f"((DD)[1]), "+f"((DD)[2]), "+f"((DD)[3]) \
                 : "r"((AA)[0]), "r"((AA)[1]), "r"((AA)[2]), "r"((AA)[3]),  \
                   "r"(B0), "r"(B1))

__device__ __forceinline__ uint32_t swz(uint32_t bo) {
    return bo ^ ((bo >> 3) & 0x70);
}

__device__ __forceinline__ int warp_incl_scan(int val, int lane) {
    #pragma unroll
    for (int off = 1; off < 32; off <<= 1) {
        int t = __shfl_up_sync(0xffffffffu, val, off);
        if (lane >= off) val += t;
    }
    return val;
}

// ---------------- x -> fp16 image ---------------------------------------------
__global__ void xconv_kernel(const float4* __restrict__ x4) {
    int i = blockIdx.x * blockDim.x + threadIdx.x;      // over NN*D/8
    if (i >= NN * D / 8) return;
    float4 a = __ldg(&x4[i * 2]);
    float4 b = __ldg(&x4[i * 2 + 1]);
    __half2 h0 = __float22half2_rn(make_float2(a.x, a.y));
    __half2 h1 = __float22half2_rn(make_float2(a.z, a.w));
    __half2 h2 = __float22half2_rn(make_float2(b.x, b.y));
    __half2 h3 = __float22half2_rn(make_float2(b.z, b.w));
    uint4 o;
    o.x = *(uint32_t*)&h0; o.y = *(uint32_t*)&h1;
    o.z = *(uint32_t*)&h2; o.w = *(uint32_t*)&h3;
    ((uint4*)g_xh)[i] = o;
}

// ---------------- CSR build ---------------------------------------------------
__global__ void zero_deg_kernel() {
    int i = blockIdx.x * blockDim.x + threadIdx.x;
    if (i < NN) g_deg[i] = 0;
}

__global__ void hist_kernel(const int* __restrict__ src) {
    int t = blockIdx.x * blockDim.x + threadIdx.x;   // 4 edges per thread
    int e = t * 4;
    if (e + 3 < EE) {
        int4 s = __ldg((const int4*)(src + e));
        atomicAdd(&g_deg[s.x], 1);
        atomicAdd(&g_deg[s.y], 1);
        atomicAdd(&g_deg[s.z], 1);
        atomicAdd(&g_deg[s.w], 1);
    } else {
        for (int q = e; q < EE; q++) atomicAdd(&g_deg[__ldg(src + q)], 1);
    }
}

__global__ __launch_bounds__(1024)
void scan_local_kernel() {
    __shared__ int warpsums[32];
    int tid = threadIdx.x, lane = tid & 31, wid = tid >> 5;
    int i = blockIdx.x * 1024 + tid;
    int v = (i < NN) ? g_deg[i] : 0;
    int val = warp_incl_scan(v, lane);
    if (lane == 31) warpsums[wid] = val;
    __syncthreads();
    if (wid == 0) warpsums[lane] = warp_incl_scan(warpsums[lane], lane);
    __syncthreads();
    int excl = val - v + (wid > 0 ? warpsums[wid - 1] : 0);
    if (i < NN) g_rowptr[i] = excl;
    if (tid == 0) g_blocksum[blockIdx.x] = warpsums[31];
}

__global__ __launch_bounds__(128)
void scan_tops_kernel() {
    __shared__ int ws[4];
    int tid = threadIdx.x, lane = tid & 31, wid = tid >> 5;
    int v = (tid < NB) ? g_blocksum[tid] : 0;
    int val = warp_incl_scan(v, lane);
    if (lane == 31) ws[wid] = val;
    __syncthreads();
    if (tid == 0) {
        int a = ws[0];
        ws[0] = 0;
        #pragma unroll
        for (int q = 1; q < 4; q++) { int t = ws[q]; ws[q] = a; a += t; }
    }
    __syncthreads();
    if (tid < NB) g_blockoff[tid] = val - v + ws[wid];
}

__global__ void scan_add_kernel() {
    int i = blockIdx.x * blockDim.x + threadIdx.x;
    if (i < NN) {
        int r = g_rowptr[i] + g_blockoff[i >> 10];
        g_rowptr[i] = r;
        g_cursor[i] = r;
    }
    if (i == 0) g_rowptr[NN] = EE;
}

__global__ void scatter_kernel(const int* __restrict__ src,
                               const int* __restrict__ dst,
                               const float* __restrict__ val) {
    int t = blockIdx.x * blockDim.x + threadIdx.x;
    int e = t * 4;
    if (e + 3 < EE) {
        int4   s = __ldg((const int4*)(src + e));
        int4   d = __ldg((const int4*)(dst + e));
        float4 v = __ldg((const float4*)(val + e));
        int p0 = atomicAdd(&g_cursor[s.x], 1);
        int p1 = atomicAdd(&g_cursor[s.y], 1);
        int p2 = atomicAdd(&g_cursor[s.z], 1);
        int p3 = atomicAdd(&g_cursor[s.w], 1);
        g_dstval[p0] = make_int2(d.x, __float_as_int(v.x));
        g_dstval[p1] = make_int2(d.y, __float_as_int(v.y));
        g_dstval[p2] = make_int2(d.z, __float_as_int(v.z));
        g_dstval[p3] = make_int2(d.w, __float_as_int(v.w));
    } else {
        for (int q = e; q < EE; q++) {
            int dd = __ldg(dst + q);
            float vv = __ldg(val + q);
            int pos = atomicAdd(&g_cursor[__ldg(src + q)], 1);
            g_dstval[pos] = make_int2(dd, __float_as_int(vv));
        }
    }
}

// ---------------- SpMM (fp16 rows): one warp per row, 8-deep unroll ----------
__global__ __launch_bounds__(256)
void spmm_kernel(const uint2* __restrict__ fin, uint2* __restrict__ fout) {
    int warp = (blockIdx.x * blockDim.x + threadIdx.x) >> 5;
    int lane = threadIdx.x & 31;
    if (warp >= NN) return;
    int beg = __ldg(&g_rowptr[warp]);
    int end = __ldg(&g_rowptr[warp + 1]);

    float4 acc = make_float4(0.f, 0.f, 0.f, 0.f);
    int j = beg;
    for (; j + 8 <= end; j += 8) {
        int2 m[8];
        uint2 a[8];
        #pragma unroll
        for (int q = 0; q < 8; q++) m[q] = __ldg(&g_dstval[j + q]);
        #pragma unroll
        for (int q = 0; q < 8; q++) a[q] = __ldg(&fin[(size_t)m[q].x * 32 + lane]);
        #pragma unroll
        for (int q = 0; q < 8; q++) {
            float v = __int_as_float(m[q].y);
            float2 fa = __half22float2(*(__half2*)&a[q].x);
            float2 fb = __half22float2(*(__half2*)&a[q].y);
            acc.x = fmaf(v, fa.x, acc.x);
            acc.y = fmaf(v, fa.y, acc.y);
            acc.z = fmaf(v, fb.x, acc.z);
            acc.w = fmaf(v, fb.y, acc.w);
        }
    }
    for (; j < end; j++) {
        int2 m = __ldg(&g_dstval[j]);
        float v = __int_as_float(m.y);
        uint2 a = __ldg(&fin[(size_t)m.x * 32 + lane]);
        float2 fa = __half22float2(*(__half2*)&a.x);
        float2 fb = __half22float2(*(__half2*)&a.y);
        acc.x = fmaf(v, fa.x, acc.x);
        acc.y = fmaf(v, fa.y, acc.y);
        acc.z = fmaf(v, fb.x, acc.z);
        acc.w = fmaf(v, fb.y, acc.w);
    }
    __half2 o0 = __float22half2_rn(make_float2(acc.x, acc.y));
    __half2 o1 = __float22half2_rn(make_float2(acc.z, acc.w));
    uint2 o;
    o.x = *(uint32_t*)&o0; o.y = *(uint32_t*)&o1;
    fout[(size_t)warp * 32 + lane] = o;
}

// ---------------- W -> fp16, pre-swizzled SW128 chunks ------------------------
__global__ void wconv_kernel(const float* __restrict__ W) {
    int i = blockIdx.x * blockDim.x + threadIdx.x;   // over 128 * 384
    if (i >= 128 * KTOT) return;
    int n = i / KTOT, k = i % KTOT;
    __half h = __float2half_rn(W[i]);
    int c = k >> 6, kk = k & 63;
    uint32_t sw = swz((uint32_t)n * 128 + kk * 2);
    *(__half*)(g_Wh + c * 16384 + sw) = h;
}

// ---------------- mma.sync GEMM: out = [xh|f1|f2] @ Wh^T + b ------------------
// CTA: 128 rows x 128 cols, K=384 in six 64-chunks. A fp16, W fp16 (1 product).
// 8 warps 4(m)x2(n), warp tile 32x64.
#define SMEM_GEMM_BYTES (1024 + 2 * 16384)

__global__ __launch_bounds__(256, 2)
void gemm_mma_kernel(const float* __restrict__ bias,
                     float* __restrict__ out) {
    extern __shared__ unsigned char dsm[];
    const int tid  = threadIdx.x;
    const int lane = tid & 31;
    const int wid  = tid >> 5;
    const int warp_m = wid & 3;
    const int warp_n = wid >> 2;
    const int rbase  = blockIdx.x * 128;

    uint32_t sb0  = smem_u32(dsm);
    uint32_t base = (sb0 + 1023) & ~1023u;
    unsigned char* gp = dsm + (base - sb0);
    const uint32_t At = base, Bh = base + 16384;

    auto load_chunk = [&](int c) {
        const uint4* fsrc = (const uint4*)((c < 2) ? g_xh : (c < 4) ? g_f1 : g_f2);
        int koff = (c & 1) * 8;                       // uint4 (16B) offset in row
        #pragma unroll
        for (int it = 0; it < 4; it++) {
            int idx = tid + it * 256;                 // 1024 x 16B
            int row = idx >> 3, c8 = idx & 7;
            int grow = rbase + row;
            uint4 v = make_uint4(0u, 0u, 0u, 0u);
            if (grow < NN) v = fsrc[(size_t)grow * 16 + koff + c8];
            *(uint4*)(gp + swz((uint32_t)row * 128 + c8 * 16)) = v;
        }
        const uint4* wh = (const uint4*)(g_Wh + c * 16384);
        uint4* pBh = (uint4*)(gp + 16384);
        #pragma unroll
        for (int it = 0; it < 4; it++) {
            int i = tid + it * 256;
            pBh[i] = wh[i];
        }
    };

    float acc[2][8][4];
    #pragma unroll
    for (int mf = 0; mf < 2; mf++)
        #pragma unroll
        for (int nf = 0; nf < 8; nf++)
            #pragma unroll
            for (int q = 0; q < 4; q++) acc[mf][nf][q] = 0.f;

    const int g = lane >> 3, r = lane & 7;
    const int a_row_off = r + (g & 1) * 8;
    const int a_k_off   = (g >> 1) * 8;
    const int b_n_off   = r + (g >> 1) * 8;
    const int b_k_off   = (g & 1) * 8;

    load_chunk(0);
    __syncthreads();

    for (int c = 0; c < 6; c++) {
        #pragma unroll
        for (int ks = 0; ks < 4; ks++) {
            const int k0 = ks * 16;
            uint32_t ah[2][4];
            #pragma unroll
            for (int mf = 0; mf < 2; mf++) {
                uint32_t sw = swz((uint32_t)(warp_m * 32 + mf * 16 + a_row_off) * 128
                                  + (k0 + a_k_off) * 2);
                LDSM4(ah[mf], At + sw);
            }
            #pragma unroll
            for (int bq = 0; bq < 4; bq++) {
                uint32_t sw = swz((uint32_t)(warp_n * 64 + bq * 16 + b_n_off) * 128
                                  + (k0 + b_k_off) * 2);
                uint32_t bh[4];
                LDSM4(bh, Bh + sw);
                #pragma unroll
                for (int mf = 0; mf < 2; mf++) {
                    MMAF16(acc[mf][bq * 2 + 0], ah[mf], bh[0], bh[1]);
                    MMAF16(acc[mf][bq * 2 + 1], ah[mf], bh[2], bh[3]);
                }
            }
        }
        if (c < 5) {
            __syncthreads();
            load_chunk(c + 1);
            __syncthreads();
        }
    }

    // ---- epilogue: bias + store ----
    const int qrow = lane >> 2, qcol = (lane & 3) * 2;
    #pragma unroll
    for (int nf = 0; nf < 8; nf++) {
        int col = warp_n * 64 + nf * 8 + qcol;
        float b0 = __ldg(&bias[col]);
        float b1 = __ldg(&bias[col + 1]);
        #pragma unroll
        for (int mf = 0; mf < 2; mf++) {
            int row0 = rbase + warp_m * 32 + mf * 16 + qrow;
            if (row0 < NN)
                *(float2*)(out + (size_t)row0 * 128 + col) =
                    make_float2(acc[mf][nf][0] + b0, acc[mf][nf][1] + b1);
            int row1 = row0 + 8;
            if (row1 < NN)
                *(float2*)(out + (size_t)row1 * 128 + col) =
                    make_float2(acc[mf][nf][2] + b0, acc[mf][nf][3] + b1);
        }
    }
}

// ---------------- launch ------------------------------------------------------
extern "C" void kernel_launch(void* const* d_in, const int* in_sizes, int n_in,
                              void* d_out, int out_size) {
    const float* x        = (const float*)d_in[0];
    const int*   edge_src = (const int*)  d_in[1];
    const int*   edge_dst = (const int*)  d_in[2];
    const float* edge_val = (const float*)d_in[3];
    const float* W        = (const float*)d_in[4];
    const float* b        = (const float*)d_in[5];
    float* out = (float*)d_out;

    static bool attr_set = false;
    if (!attr_set) {
        cudaFuncSetAttribute(gemm_mma_kernel,
                             cudaFuncAttributeMaxDynamicSharedMemorySize,
                             SMEM_GEMM_BYTES);
        attr_set = true;
    }

    uint2 *xhp, *f1p, *f2p;
    cudaGetSymbolAddress((void**)&xhp, g_xh);
    cudaGetSymbolAddress((void**)&f1p, g_f1);
    cudaGetSymbolAddress((void**)&f2p, g_f2);

    // 1) Prep: W fp16 image, x fp16 image, CSR build with parallel scan
    wconv_kernel<<<(128 * KTOT + 255) / 256, 256>>>(W);
    xconv_kernel<<<(NN * D / 8 + 255) / 256, 256>>>((const float4*)x);
    zero_deg_kernel<<<(NN + 255) / 256, 256>>>();
    hist_kernel<<<(EE / 4 + 255) / 256, 256>>>(edge_src);
    scan_local_kernel<<<NB, 1024>>>();
    scan_tops_kernel<<<1, 128>>>();
    scan_add_kernel<<<(NN + 255) / 256, 256>>>();
    scatter_kernel<<<(EE / 4 + 255) / 256, 256>>>(edge_src, edge_dst, edge_val);

    // 2) Two SpMM hops (fp16 gather, fp32 accumulate)
    int spmm_blocks = (NN + 7) / 8;
    spmm_kernel<<<spmm_blocks, 256>>>(xhp, f1p);
    spmm_kernel<<<spmm_blocks, 256>>>(f1p, f2p);

    // 3) Tensor-core dense layer on [xh | f1 | f2]
    gemm_mma_kernel<<<(NN + 127) / 128, 256, SMEM_GEMM_BYTES>>>(b, out);
}